// round 2
// baseline (speedup 1.0000x reference)
#include <cuda_runtime.h>

#define BB 8
#define CC 128
#define WW 4096
#define DD 16

typedef unsigned long long ull;

// Scratch (allocation-free rule: __device__ globals)
__device__ float g_q[BB*WW*DD];      // [b][w][d]
__device__ float g_k[BB*WW*DD];      // [b][w][d]
__device__ float g_v[BB*CC*WW];      // [b][c][w]
__device__ float g_m[BB*WW];
__device__ float g_linv[BB*WW];

// ---- packed f32x2 helpers (SASS FFMA2; only reachable via PTX) ----
__device__ __forceinline__ void fma2(ull& d, ull a, ull b) {
    asm("fma.rn.f32x2 %0, %1, %2, %0;" : "+l"(d) : "l"(a), "l"(b));
}
__device__ __forceinline__ ull pack2(float a, float b) {
    ull r; asm("mov.b64 %0, {%1, %2};" : "=l"(r) : "f"(a), "f"(b)); return r;
}
__device__ __forceinline__ void unpack2(float& lo, float& hi, ull v) {
    asm("mov.b64 {%0, %1}, %2;" : "=f"(lo), "=f"(hi) : "l"(v));
}

// Fast e^x for x <= 0. Pure fixed-latency ops: no MUFU, no CVT.
__device__ __forceinline__ float fexp(float x) {
    float y = fmaxf(x * 1.4426950408889634f, -126.0f);
    float z = y + 12582912.0f;              // round-to-nearest-int in mantissa
    float r = z - 12582912.0f;
    float f = y - r;
    int   e = __float_as_int(z) << 23;      // integer part scaled to exponent
    float p = 1.3333558146e-3f;
    p = fmaf(p, f, 9.6181291076e-3f);
    p = fmaf(p, f, 5.5504108665e-2f);
    p = fmaf(p, f, 2.4022650696e-1f);
    p = fmaf(p, f, 6.9314718056e-1f);
    p = fmaf(p, f, 1.0f);
    return __int_as_float(__float_as_int(p) + e);
}

// ---------------------------------------------------------------------------
// Kernel 1: fused projections. Block: (b, 128-w tile), 512 threads.
// V GEMM uses f32x2 FMA with 4c x 8w micro-tiles.
// ---------------------------------------------------------------------------
__global__ void __launch_bounds__(512) k_proj(
    const float* __restrict__ x,
    const float* __restrict__ Wq, const float* __restrict__ bq,
    const float* __restrict__ Wk, const float* __restrict__ bk,
    const float* __restrict__ Wv, const float* __restrict__ bv)
{
    extern __shared__ float sm[];
    float* xs  = sm;                 // [128][128]
    float* wvs = sm + CC*128;        // [128][129]  (pad kills bank conflict)
    float* wqk = wvs + CC*129;       // [2][16][128]
    const int b   = blockIdx.y;
    const int w0  = blockIdx.x * 128;
    const int tid = threadIdx.x;

    for (int i = tid; i < CC*128; i += 512) {
        int c = i >> 7, wl = i & 127;
        xs[i] = x[(b*CC + c)*WW + w0 + wl];
    }
    for (int i = tid; i < CC*CC; i += 512) {
        int o = i >> 7, c = i & 127;
        wvs[o*129 + c] = Wv[i];
    }
    for (int i = tid; i < DD*CC; i += 512) { wqk[i] = Wq[i]; wqk[DD*CC + i] = Wk[i]; }
    __syncthreads();

    // ---- V projection: 128x128 GEMM, 4x8 micro-tiles over 512 threads ----
    {
        const int c0  = (tid >> 4) * 4;      // 32 groups of 4 output channels
        const int wl0 = (tid & 15) * 8;
        ull acc[4][4];
        #pragma unroll
        for (int ci = 0; ci < 4; ci++) {
            float bvv = bv[c0 + ci];
            ull bb = pack2(bvv, bvv);
            #pragma unroll
            for (int k = 0; k < 4; k++) acc[ci][k] = bb;
        }
        for (int c = 0; c < CC; c++) {
            ulonglong2 b01 = *(const ulonglong2*)&xs[c*128 + wl0];
            ulonglong2 b23 = *(const ulonglong2*)&xs[c*128 + wl0 + 4];
            #pragma unroll
            for (int ci = 0; ci < 4; ci++) {
                float a = wvs[(c0 + ci)*129 + c];
                ull aa = pack2(a, a);
                fma2(acc[ci][0], aa, b01.x);
                fma2(acc[ci][1], aa, b01.y);
                fma2(acc[ci][2], aa, b23.x);
                fma2(acc[ci][3], aa, b23.y);
            }
        }
        #pragma unroll
        for (int ci = 0; ci < 4; ci++) {
            float r[8];
            unpack2(r[0], r[1], acc[ci][0]);
            unpack2(r[2], r[3], acc[ci][1]);
            unpack2(r[4], r[5], acc[ci][2]);
            unpack2(r[6], r[7], acc[ci][3]);
            float* op = &g_v[(size_t)(b*CC + c0 + ci)*WW + w0 + wl0];
            *(float4*)(op)     = make_float4(r[0], r[1], r[2], r[3]);
            *(float4*)(op + 4) = make_float4(r[4], r[5], r[6], r[7]);
        }
    }

    // ---- Q / K projections: threads [0,128) q, [128,256) k ----
    if (tid < 256) {
        const int wl   = tid & 127;
        const int half = tid >> 7;
        const float* Wm   = &wqk[half*DD*CC];
        const float* bias = half ? bk : bq;
        float acc[DD];
        #pragma unroll
        for (int d = 0; d < DD; d++) acc[d] = bias[d];
        for (int c = 0; c < CC; c++) {
            float xv = xs[c*128 + wl];
            #pragma unroll
            for (int d = 0; d < DD; d++) acc[d] = fmaf(Wm[d*CC + c], xv, acc[d]);
        }
        float* op = (half ? g_k : g_q) + (size_t)(b*WW + w0 + wl)*DD;
        #pragma unroll
        for (int d = 0; d < DD; d += 4)
            *(float4*)&op[d] = make_float4(acc[d], acc[d+1], acc[d+2], acc[d+3]);
    }
}

// ---------------------------------------------------------------------------
// Kernel 2: per-row softmax stats (online max/sum). Unchanged structure.
// ---------------------------------------------------------------------------
__global__ void __launch_bounds__(256) k_stats()
{
    __shared__ float ks[128*DD];
    const int b   = blockIdx.y;
    const int j0  = blockIdx.x * 32;
    const int tid = threadIdx.x;
    const int jl   = tid >> 3;
    const int lane = tid & 7;
    const int j = j0 + jl;

    const float4* qr = (const float4*)&g_q[(size_t)(b*WW + j)*DD];
    const float4 q0 = qr[0], q1 = qr[1], q2 = qr[2], q3 = qr[3];

    float m = -1e30f, l = 0.0f;

    for (int w0 = 0; w0 < WW; w0 += 128) {
        __syncthreads();
        for (int i = tid; i < 128*DD; i += 256)
            ks[i] = g_k[(size_t)(b*WW + w0)*DD + i];
        __syncthreads();
        #pragma unroll 4
        for (int ii = 0; ii < 16; ii++) {
            int wl = ii*8 + lane;
            const float4* kr = (const float4*)&ks[wl*DD];
            float4 k0 = kr[0], k1 = kr[1], k2 = kr[2], k3 = kr[3];
            float s = q0.x*k0.x + q0.y*k0.y + q0.z*k0.z + q0.w*k0.w
                    + q1.x*k1.x + q1.y*k1.y + q1.z*k1.z + q1.w*k1.w
                    + q2.x*k2.x + q2.y*k2.y + q2.z*k2.z + q2.w*k2.w
                    + q3.x*k3.x + q3.y*k3.y + q3.z*k3.z + q3.w*k3.w;
            s *= 0.25f;
            if (s <= m) {
                l += fexp(s - m);
            } else {
                l = fmaf(l, fexp(m - s), 1.0f);
                m = s;
            }
        }
    }
    #pragma unroll
    for (int off = 4; off; off >>= 1) {
        float m2 = __shfl_down_sync(0xffffffffu, m, off, 8);
        float l2 = __shfl_down_sync(0xffffffffu, l, off, 8);
        float M = fmaxf(m, m2);
        l = l * fexp(m - M) + l2 * fexp(m2 - M);
        m = M;
    }
    if (lane == 0) {
        g_m[b*WW + j]    = m;
        g_linv[b*WW + j] = 1.0f / l;
    }
}

// ---------------------------------------------------------------------------
// Kernel 3: context GEMM with f32x2 FMA. Block: (b, 128-w tile), 256 thr.
// V is stored DUPLICATED in smem so LDS.64 yields the {v,v} broadcast pair
// with zero pack-MOVs. 8c x 8w register tile (4 f32x2 per c).
// ---------------------------------------------------------------------------
__global__ void __launch_bounds__(256, 2) k_ctx(const float* __restrict__ x,
                                                float* __restrict__ out)
{
    extern __shared__ float sm2[];
    float* vs2 = sm2;                  // [128][66]: vs2[c*66+2jj] = vs2[..+1] = v
    float* ps  = vs2 + 128*66;         // [32][132]
    float* ksh = ps  + 32*132;         // [128][16]
    float* qs  = ksh + 128*DD;         // [32][16]
    float* msh = qs  + 32*DD;          // [32]
    float* lsh = msh + 32;             // [32]

    const int b   = blockIdx.y;
    const int wg0 = blockIdx.x * 128;
    const int tid = threadIdx.x;

    for (int i = tid; i < 128*DD; i += 256)
        ksh[i] = g_k[(size_t)(b*WW + wg0)*DD + i];

    ull acc[8][4];
    #pragma unroll
    for (int ci = 0; ci < 8; ci++)
        #pragma unroll
        for (int k = 0; k < 4; k++) acc[ci][k] = 0ull;

    const int tc = tid >> 4, tw = tid & 15;
    const int c0 = tc * 8, wl0 = tw * 8;

    for (int j0 = 0; j0 < WW; j0 += 32) {
        __syncthreads();
        for (int i = tid; i < 128*32; i += 256) {
            int c = i >> 5, jj = i & 31;
            float v = g_v[(size_t)(b*CC + c)*WW + j0 + jj];
            *(float2*)&vs2[c*66 + 2*jj] = make_float2(v, v);
        }
        for (int i = tid; i < 32*DD; i += 256)
            qs[i] = g_q[(size_t)(b*WW + j0)*DD + i];
        if (tid < 32) {
            msh[tid] = g_m[b*WW + j0 + tid];
            lsh[tid] = g_linv[b*WW + j0 + tid];
        }
        __syncthreads();

        // P tile 32 x 128 (packed q.k dot)
        for (int e = tid; e < 32*128; e += 256) {
            int j = e >> 7, wl = e & 127;
            const ull* qr = (const ull*)&qs[j*DD];
            const ull* kr = (const ull*)&ksh[wl*DD];
            ull s0 = 0ull, s1 = 0ull;
            fma2(s0, qr[0], kr[0]); fma2(s1, qr[1], kr[1]);
            fma2(s0, qr[2], kr[2]); fma2(s1, qr[3], kr[3]);
            fma2(s0, qr[4], kr[4]); fma2(s1, qr[5], kr[5]);
            fma2(s0, qr[6], kr[6]); fma2(s1, qr[7], kr[7]);
            float a0, a1, b0, b1;
            unpack2(a0, a1, s0); unpack2(b0, b1, s1);
            float s = (a0 + a1) + (b0 + b1);
            ps[j*132 + wl] = fexp(fmaf(s, 0.25f, -msh[j])) * lsh[j];
        }
        __syncthreads();

        #pragma unroll 4
        for (int jj = 0; jj < 32; jj++) {
            ulonglong2 p01 = *(const ulonglong2*)&ps[jj*132 + wl0];
            ulonglong2 p23 = *(const ulonglong2*)&ps[jj*132 + wl0 + 4];
            #pragma unroll
            for (int ci = 0; ci < 8; ci++) {
                ull aa = *(const ull*)&vs2[(c0 + ci)*66 + 2*jj];
                fma2(acc[ci][0], aa, p01.x);
                fma2(acc[ci][1], aa, p01.y);
                fma2(acc[ci][2], aa, p23.x);
                fma2(acc[ci][3], aa, p23.y);
            }
        }
    }

    // epilogue: residual add + store
    #pragma unroll
    for (int ci = 0; ci < 8; ci++) {
        float r[8];
        unpack2(r[0], r[1], acc[ci][0]);
        unpack2(r[2], r[3], acc[ci][1]);
        unpack2(r[4], r[5], acc[ci][2]);
        unpack2(r[6], r[7], acc[ci][3]);
        const float* xp = &x[(size_t)(b*CC + c0 + ci)*WW + wg0 + wl0];
        float*       op = &out[(size_t)(b*CC + c0 + ci)*WW + wg0 + wl0];
        float4 x0 = *(const float4*)xp;
        float4 x1 = *(const float4*)(xp + 4);
        *(float4*)op       = make_float4(r[0] + x0.x, r[1] + x0.y, r[2] + x0.z, r[3] + x0.w);
        *(float4*)(op + 4) = make_float4(r[4] + x1.x, r[5] + x1.y, r[6] + x1.z, r[7] + x1.w);
    }
}

// ---------------------------------------------------------------------------
extern "C" void kernel_launch(void* const* d_in, const int* in_sizes, int n_in,
                              void* d_out, int out_size)
{
    const float* x  = (const float*)d_in[0];
    const float* Wq = (const float*)d_in[1];
    const float* bq = (const float*)d_in[2];
    const float* Wk = (const float*)d_in[3];
    const float* bk = (const float*)d_in[4];
    const float* Wv = (const float*)d_in[5];
    const float* bv = (const float*)d_in[6];
    float* out = (float*)d_out;

    const int smem_proj = (CC*128 + CC*129 + 2*DD*CC) * 4;
    const int smem_ctx  = (128*66 + 32*132 + 128*DD + 32*DD + 64) * 4;
    cudaFuncSetAttribute(k_proj, cudaFuncAttributeMaxDynamicSharedMemorySize, smem_proj);
    cudaFuncSetAttribute(k_ctx,  cudaFuncAttributeMaxDynamicSharedMemorySize, smem_ctx);

    dim3 g1(WW/128, BB);
    k_proj<<<g1, 512, smem_proj>>>(x, Wq, bq, Wk, bk, Wv, bv);

    dim3 g2(WW/32, BB);
    k_stats<<<g2, 256>>>();

    dim3 g3(WW/128, BB);
    k_ctx<<<g3, 256, smem_ctx>>>(x, out);
}

// round 5
// speedup vs baseline: 8.3759x; 8.3759x over previous
#include <cuda_runtime.h>
#include <cuda_bf16.h>
#include <cstdint>

#define BB 8
#define CC 128
#define WW 4096
#define DD 16

// 0.25 (= D^-0.5) * log2(e): folded into q so softmax uses exp2 directly.
#define QSCALE 0.3606737602222409f

typedef unsigned long long ull;

// ---- scratch (__device__ globals; no allocs allowed) ----------------------
__device__ __nv_bfloat16 g_q[(size_t)BB*WW*DD];   // [b][w][d], pre-scaled
__device__ __nv_bfloat16 g_k[(size_t)BB*WW*DD];   // [b][w][d]
__device__ __nv_bfloat16 g_v[(size_t)BB*CC*WW];   // [b][c][w]
__device__ float g_linv[BB*WW];                    // 1 / row sum of exp2(S)

// ---- helpers --------------------------------------------------------------
__device__ __forceinline__ uint32_t smem_u32(const void* p) {
    uint32_t a;
    asm("{ .reg .u64 t; cvta.to.shared.u64 t, %1; cvt.u32.u64 %0, t; }"
        : "=r"(a) : "l"(p));
    return a;
}
__device__ __forceinline__ uint32_t bf2u(__nv_bfloat162 h) {
    return *reinterpret_cast<uint32_t*>(&h);
}
__device__ __forceinline__ float fexp2(float x) {   // MUFU ex2 (approx ok: 1e-3 budget)
    float y; asm("ex2.approx.f32 %0, %1;" : "=f"(y) : "f"(x)); return y;
}

// packed f32x2 fma (k_proj only)
__device__ __forceinline__ void fma2(ull& d, ull a, ull b) {
    asm("fma.rn.f32x2 %0, %1, %2, %0;" : "+l"(d) : "l"(a), "l"(b));
}
__device__ __forceinline__ ull pack2(float a, float b) {
    ull r; asm("mov.b64 %0, {%1, %2};" : "=l"(r) : "f"(a), "f"(b)); return r;
}
__device__ __forceinline__ void unpack2(float& lo, float& hi, ull v) {
    asm("mov.b64 {%0, %1}, %2;" : "=f"(lo), "=f"(hi) : "l"(v));
}

// ---- mma.sync m16n8k16 bf16 (A row-major, B col-major, f32 accum) ---------
__device__ __forceinline__ void mma_acc(float* d, const uint32_t* a,
                                        uint32_t b0, uint32_t b1) {
    asm volatile("mma.sync.aligned.m16n8k16.row.col.f32.bf16.bf16.f32 "
        "{%0,%1,%2,%3}, {%4,%5,%6,%7}, {%8,%9}, {%0,%1,%2,%3};"
        : "+f"(d[0]), "+f"(d[1]), "+f"(d[2]), "+f"(d[3])
        : "r"(a[0]), "r"(a[1]), "r"(a[2]), "r"(a[3]), "r"(b0), "r"(b1));
}
__device__ __forceinline__ void mma_z(float* d, const uint32_t* a,
                                      uint32_t b0, uint32_t b1) {
    asm volatile("mma.sync.aligned.m16n8k16.row.col.f32.bf16.bf16.f32 "
        "{%0,%1,%2,%3}, {%4,%5,%6,%7}, {%8,%9}, {%10,%10,%10,%10};"
        : "=f"(d[0]), "=f"(d[1]), "=f"(d[2]), "=f"(d[3])
        : "r"(a[0]), "r"(a[1]), "r"(a[2]), "r"(a[3]), "r"(b0), "r"(b1),
          "f"(0.0f));
}

// ---- cp.async -------------------------------------------------------------
#define CP16(dst, src) asm volatile("cp.async.cg.shared.global [%0], [%1], 16;" :: "r"(dst), "l"(src))
#define CP8(dst, src)  asm volatile("cp.async.ca.shared.global [%0], [%1], 8;"  :: "r"(dst), "l"(src))
#define CP_COMMIT()    asm volatile("cp.async.commit_group;" ::: "memory")
#define CP_WAIT0()     asm volatile("cp.async.wait_group 0;" ::: "memory")

// ===========================================================================
// Kernel 1: projections -> bf16 q' (pre-scaled), k, v.
// ===========================================================================
__global__ void __launch_bounds__(512) k_proj(
    const float* __restrict__ x,
    const float* __restrict__ Wq, const float* __restrict__ bq,
    const float* __restrict__ Wk, const float* __restrict__ bk,
    const float* __restrict__ Wv, const float* __restrict__ bv)
{
    extern __shared__ float sm[];
    float* xs  = sm;                 // [128][128]
    float* wvs = sm + CC*128;        // [128][129]
    float* wqk = wvs + CC*129;       // [2][16][128]
    const int b   = blockIdx.y;
    const int w0  = blockIdx.x * 128;
    const int tid = threadIdx.x;

    for (int i = tid; i < CC*128; i += 512) {
        int c = i >> 7, wl = i & 127;
        xs[i] = x[(size_t)(b*CC + c)*WW + w0 + wl];
    }
    for (int i = tid; i < CC*CC; i += 512) {
        int o = i >> 7, c = i & 127;
        wvs[o*129 + c] = Wv[i];
    }
    for (int i = tid; i < DD*CC; i += 512) { wqk[i] = Wq[i]; wqk[DD*CC + i] = Wk[i]; }
    __syncthreads();

    {   // V projection
        const int c0  = (tid >> 4) * 4;
        const int wl0 = (tid & 15) * 8;
        ull acc[4][4];
        #pragma unroll
        for (int ci = 0; ci < 4; ci++) {
            float bvv = bv[c0 + ci];
            ull bb = pack2(bvv, bvv);
            #pragma unroll
            for (int k = 0; k < 4; k++) acc[ci][k] = bb;
        }
        for (int c = 0; c < CC; c++) {
            ulonglong2 b01 = *(const ulonglong2*)&xs[c*128 + wl0];
            ulonglong2 b23 = *(const ulonglong2*)&xs[c*128 + wl0 + 4];
            #pragma unroll
            for (int ci = 0; ci < 4; ci++) {
                float a = wvs[(c0 + ci)*129 + c];
                ull aa = pack2(a, a);
                fma2(acc[ci][0], aa, b01.x);
                fma2(acc[ci][1], aa, b01.y);
                fma2(acc[ci][2], aa, b23.x);
                fma2(acc[ci][3], aa, b23.y);
            }
        }
        #pragma unroll
        for (int ci = 0; ci < 4; ci++) {
            float r[8];
            unpack2(r[0], r[1], acc[ci][0]);
            unpack2(r[2], r[3], acc[ci][1]);
            unpack2(r[4], r[5], acc[ci][2]);
            unpack2(r[6], r[7], acc[ci][3]);
            uint4 o;
            o.x = bf2u(__floats2bfloat162_rn(r[0], r[1]));
            o.y = bf2u(__floats2bfloat162_rn(r[2], r[3]));
            o.z = bf2u(__floats2bfloat162_rn(r[4], r[5]));
            o.w = bf2u(__floats2bfloat162_rn(r[6], r[7]));
            *(uint4*)(g_v + (size_t)(b*CC + c0 + ci)*WW + w0 + wl0) = o;
        }
    }

    if (tid < 256) {   // Q / K projections
        const int wl   = tid & 127;
        const int half = tid >> 7;
        const float* Wm   = &wqk[half*DD*CC];
        const float* bias = half ? bk : bq;
        float acc[DD];
        #pragma unroll
        for (int d = 0; d < DD; d++) acc[d] = bias[d];
        for (int c = 0; c < CC; c++) {
            float xv = xs[c*128 + wl];
            #pragma unroll
            for (int d = 0; d < DD; d++) acc[d] = fmaf(Wm[d*CC + c], xv, acc[d]);
        }
        const float scale = half ? 1.0f : QSCALE;
        #pragma unroll
        for (int d = 0; d < DD; d++) acc[d] *= scale;
        __nv_bfloat16* op = (half ? g_k : g_q) + (size_t)(b*WW + w0 + wl)*DD;
        uint4 o0, o1;
        o0.x = bf2u(__floats2bfloat162_rn(acc[0],  acc[1]));
        o0.y = bf2u(__floats2bfloat162_rn(acc[2],  acc[3]));
        o0.z = bf2u(__floats2bfloat162_rn(acc[4],  acc[5]));
        o0.w = bf2u(__floats2bfloat162_rn(acc[6],  acc[7]));
        o1.x = bf2u(__floats2bfloat162_rn(acc[8],  acc[9]));
        o1.y = bf2u(__floats2bfloat162_rn(acc[10], acc[11]));
        o1.z = bf2u(__floats2bfloat162_rn(acc[12], acc[13]));
        o1.w = bf2u(__floats2bfloat162_rn(acc[14], acc[15]));
        *(uint4*)op       = o0;
        *(uint4*)(op + 8) = o1;
    }
}

// ===========================================================================
// Kernel 2: row sums l_j = sum_w exp2(S[j,w]);  g_linv = 1/l.
// CTA = (b, 128 j-rows), 8 warps: warp owns j rows [wid*16, wid*16+16).
// SKD=48: 16B-aligned cp.async dsts AND conflict-free fragment loads (4g+t).
// ===========================================================================
#define SKD 48     // row stride (bytes) for 16-half d-rows (32B data + 16 pad)
__global__ void __launch_bounds__(256, 2) k_stats()
{
    __shared__ __align__(16) char smc[3*128*SKD];
    const uint32_t smb = smem_u32(smc);
    const int tid = threadIdx.x;
    const int wid = tid >> 5;
    const int lane = tid & 31;
    const int g = lane >> 2, t = lane & 3;
    const int b = blockIdx.y, j0 = blockIdx.x * 128;
    const uint32_t QS = smb, KS = smb + 128*SKD;

    {   // q tile: row r = j0+r, 32B per row
        int r = tid >> 1, h = tid & 1;
        CP16(QS + r*SKD + h*16, (const char*)(g_q + (size_t)(b*WW + j0 + r)*DD) + h*16);
    }
    {   // k tile wt=0 into buf 0
        int r = tid >> 1, h = tid & 1;
        CP16(KS + r*SKD + h*16, (const char*)(g_k + (size_t)(b*WW + r)*DD) + h*16);
    }
    CP_COMMIT(); CP_WAIT0();
    __syncthreads();

    // A fragments (q rows for this warp), loaded once
    uint32_t a[4];
    {
        const char* r0 = smc + (wid*16 + g)*SKD + t*4;
        const char* r1 = smc + (wid*16 + g + 8)*SKD + t*4;
        a[0] = *(const uint32_t*)r0;
        a[1] = *(const uint32_t*)r1;
        a[2] = *(const uint32_t*)(r0 + 16);
        a[3] = *(const uint32_t*)(r1 + 16);
    }

    float l0 = 0.0f, l1 = 0.0f;
    for (int wt = 0; wt < 32; wt++) {
        const char* kb = smc + 128*SKD + (wt & 1)*(128*SKD);
        if (wt + 1 < 32) {
            int r = tid >> 1, h = tid & 1;
            CP16(KS + ((wt + 1) & 1)*(128*SKD) + r*SKD + h*16,
                 (const char*)(g_k + (size_t)(b*WW + (wt + 1)*128 + r)*DD) + h*16);
        }
        CP_COMMIT();
        #pragma unroll
        for (int nt = 0; nt < 16; nt++) {
            const char* baddr = kb + (nt*8 + g)*SKD + t*4;
            uint32_t b0 = *(const uint32_t*)baddr;
            uint32_t b1 = *(const uint32_t*)(baddr + 16);
            float d[4];
            mma_z(d, a, b0, b1);
            l0 += fexp2(d[0]) + fexp2(d[1]);
            l1 += fexp2(d[2]) + fexp2(d[3]);
        }
        CP_WAIT0();
        __syncthreads();
    }
    // reduce across the 4 lanes sharing each row
    #pragma unroll
    for (int off = 1; off < 4; off <<= 1) {
        l0 += __shfl_down_sync(0xffffffffu, l0, off, 4);
        l1 += __shfl_down_sync(0xffffffffu, l1, off, 4);
    }
    if (t == 0) {
        g_linv[b*WW + j0 + wid*16 + g]     = 1.0f / l0;
        g_linv[b*WW + j0 + wid*16 + g + 8] = 1.0f / l1;
    }
}

// ===========================================================================
// Kernel 3: context + residual. CTA = (b, 128-w tile), 8 warps.
// Per 64-j tile: QK mma S'[w][j] (A=k fixed, B=q) -> Pt[w][j] bf16 in smem
// -> PV mma out[c][w] += v[c][j] x Pt (A=v, B=Pt). cp.async double buffers.
// smem map (bytes): ks@0 (6144), qs@6144 (2x3072), vs@12288 (2x18432),
//                   Pt@49152 (18432), linv@67584 (16384). total 83968.
// ===========================================================================
#define SPJ 144            // row stride (bytes) for 64-half j-rows
#define OF_KS 0
#define OF_QS 6144
#define OF_VS 12288
#define OF_PT 49152
#define OF_LV 67584

__global__ void __launch_bounds__(256, 2) k_ctx(const float* __restrict__ x,
                                                float* __restrict__ out)
{
    extern __shared__ __align__(16) char smc[];
    const uint32_t smb = smem_u32(smc);
    const int tid = threadIdx.x;
    const int wid = tid >> 5;
    const int lane = tid & 31;
    const int g = lane >> 2, t = lane & 3;
    const int b = blockIdx.y, w0 = blockIdx.x * 128;

    // ---- preload: ks (fixed), linv (whole row range), q/v tile jt=0 ----
    {
        int r = tid >> 1, h = tid & 1;
        CP16(smb + OF_KS + r*SKD + h*16,
             (const char*)(g_k + (size_t)(b*WW + w0 + r)*DD) + h*16);
    }
    #pragma unroll
    for (int i = 0; i < 4; i++) {
        int idx = tid + i*256;
        CP16(smb + OF_LV + idx*16, (const char*)(g_linv + b*WW) + idx*16);
    }
    {   // q tile jt0: 64 rows x 32B
        int r = tid >> 2, h = tid & 3;
        CP8(smb + OF_QS + r*SKD + h*8,
            (const char*)(g_q + (size_t)(b*WW + r)*DD) + h*8);
    }
    #pragma unroll
    for (int i = 0; i < 4; i++) {   // v tile jt0: 128 rows x 128B
        int cid = tid + i*256;
        int c = cid >> 3, ch = cid & 7;
        CP16(smb + OF_VS + c*SPJ + ch*16,
             (const char*)(g_v + (size_t)(b*CC + c)*WW) + ch*16);
    }
    CP_COMMIT(); CP_WAIT0();
    __syncthreads();

    // A fragments for QK (k rows = this warp's 16 w rows), fixed
    uint32_t ak[4];
    {
        const char* r0 = smc + OF_KS + (wid*16 + g)*SKD + t*4;
        const char* r1 = smc + OF_KS + (wid*16 + g + 8)*SKD + t*4;
        ak[0] = *(const uint32_t*)r0;
        ak[1] = *(const uint32_t*)r1;
        ak[2] = *(const uint32_t*)(r0 + 16);
        ak[3] = *(const uint32_t*)(r1 + 16);
    }

    const int c0w = (wid & 3) * 32;        // PV: warp channel base
    const int wc0 = (wid >> 2) * 64;       // PV: warp w base (within tile)
    float acc[2][8][4];
    #pragma unroll
    for (int mt = 0; mt < 2; mt++)
        #pragma unroll
        for (int nt = 0; nt < 8; nt++)
            #pragma unroll
            for (int e = 0; e < 4; e++) acc[mt][nt][e] = 0.0f;

    for (int jt = 0; jt < 64; jt++) {
        const int buf = jt & 1;
        const int j0 = jt * 64;

        if (jt + 1 < 64) {   // prefetch next q/v into buf^1
            const int jn = j0 + 64, nb = buf ^ 1;
            int r = tid >> 2, h = tid & 3;
            CP8(smb + OF_QS + nb*3072 + r*SKD + h*8,
                (const char*)(g_q + (size_t)(b*WW + jn + r)*DD) + h*8);
            #pragma unroll
            for (int i = 0; i < 4; i++) {
                int cid = tid + i*256;
                int c = cid >> 3, ch = cid & 7;
                CP16(smb + OF_VS + nb*18432 + c*SPJ + ch*16,
                     (const char*)(g_v + (size_t)(b*CC + c)*WW + jn) + ch*16);
            }
        }
        CP_COMMIT();

        // ---- QK: S'[w][j] for warp's 16 w rows x 64 j, epilogue -> Pt ----
        const char* qb = smc + OF_QS + buf*3072;
        const float* lv = (const float*)(smc + OF_LV) + j0;
        #pragma unroll
        for (int nt = 0; nt < 8; nt++) {
            const char* baddr = qb + (nt*8 + g)*SKD + t*4;
            uint32_t b0 = *(const uint32_t*)baddr;
            uint32_t b1 = *(const uint32_t*)(baddr + 16);
            float d[4];
            mma_z(d, ak, b0, b1);
            float2 l01 = *(const float2*)(lv + nt*8 + 2*t);
            float p0 = fexp2(d[0]) * l01.x;
            float p1 = fexp2(d[1]) * l01.y;
            float p2 = fexp2(d[2]) * l01.x;
            float p3 = fexp2(d[3]) * l01.y;
            *(uint32_t*)(smc + OF_PT + (wid*16 + g)*SPJ     + (nt*8 + 2*t)*2) =
                bf2u(__floats2bfloat162_rn(p0, p1));
            *(uint32_t*)(smc + OF_PT + (wid*16 + g + 8)*SPJ + (nt*8 + 2*t)*2) =
                bf2u(__floats2bfloat162_rn(p2, p3));
        }
        __syncthreads();   // Pt complete (prev PV finished at last sync)

        // ---- PV: acc[c][w] += v[c][j] * Pt[w][j] ----
        #pragma unroll
        for (int k0 = 0; k0 < 4; k0++) {
            uint32_t av[2][4];
            #pragma unroll
            for (int mt = 0; mt < 2; mt++) {
                const char* r0 = smc + OF_VS + buf*18432
                               + (c0w + mt*16 + g)*SPJ + k0*32 + t*4;
                const char* r1 = r0 + 8*SPJ;
                av[mt][0] = *(const uint32_t*)r0;
                av[mt][1] = *(const uint32_t*)r1;
                av[mt][2] = *(const uint32_t*)(r0 + 16);
                av[mt][3] = *(const uint32_t*)(r1 + 16);
            }
            #pragma unroll
            for (int nt = 0; nt < 8; nt++) {
                const char* pb = smc + OF_PT + (wc0 + nt*8 + g)*SPJ + k0*32 + t*4;
                uint32_t b0 = *(const uint32_t*)pb;
                uint32_t b1 = *(const uint32_t*)(pb + 16);
                mma_acc(acc[0][nt], av[0], b0, b1);
                mma_acc(acc[1][nt], av[1], b0, b1);
            }
        }
        CP_WAIT0();
        __syncthreads();   // buf^1 tiles landed; Pt free for next iter
    }

    // ---- epilogue: out = acc + x ----
    #pragma unroll
    for (int mt = 0; mt < 2; mt++) {
        #pragma unroll
        for (int nt = 0; nt < 8; nt++) {
            int c  = c0w + mt*16 + g;
            int wc = w0 + wc0 + nt*8 + 2*t;
            size_t i0 = (size_t)(b*CC + c)*WW + wc;
            size_t i1 = i0 + 8*WW;
            float2 x0 = *(const float2*)(x + i0);
            float2 x1 = *(const float2*)(x + i1);
            *(float2*)(out + i0) = make_float2(acc[mt][nt][0] + x0.x,
                                               acc[mt][nt][1] + x0.y);
            *(float2*)(out + i1) = make_float2(acc[mt][nt][2] + x1.x,
                                               acc[mt][nt][3] + x1.y);
        }
    }
}

// ===========================================================================
extern "C" void kernel_launch(void* const* d_in, const int* in_sizes, int n_in,
                              void* d_out, int out_size)
{
    const float* x  = (const float*)d_in[0];
    const float* Wq = (const float*)d_in[1];
    const float* bq = (const float*)d_in[2];
    const float* Wk = (const float*)d_in[3];
    const float* bk = (const float*)d_in[4];
    const float* Wv = (const float*)d_in[5];
    const float* bv = (const float*)d_in[6];
    float* out = (float*)d_out;

    const int smem_proj = (CC*128 + CC*129 + 2*DD*CC) * 4;
    const int smem_ctx  = 83968;
    cudaFuncSetAttribute(k_proj, cudaFuncAttributeMaxDynamicSharedMemorySize, smem_proj);
    cudaFuncSetAttribute(k_ctx,  cudaFuncAttributeMaxDynamicSharedMemorySize, smem_ctx);

    dim3 g(WW/128, BB);
    k_proj <<<g, 512, smem_proj>>>(x, Wq, bq, Wk, bk, Wv, bv);
    k_stats<<<g, 256>>>();
    k_ctx  <<<g, 256, smem_ctx>>>(x, out);
}

// round 6
// speedup vs baseline: 10.1736x; 1.2146x over previous
#include <cuda_runtime.h>
#include <cuda_bf16.h>
#include <cstdint>

#define BB 8
#define CC 128
#define WW 4096
#define DD 16

// 0.25 (= D^-0.5) * log2(e): folded into q so softmax uses exp2 directly.
#define QSCALE 0.3606737602222409f

typedef unsigned long long ull;

// ---- scratch (__device__ globals; no allocs allowed) ----------------------
__device__ __nv_bfloat16 g_q[(size_t)BB*WW*DD];   // [b][w][d], pre-scaled
__device__ __nv_bfloat16 g_k[(size_t)BB*WW*DD];   // [b][w][d]
__device__ __nv_bfloat16 g_v[(size_t)BB*CC*WW];   // [b][c][w]
__device__ float g_linv[BB*WW];                    // 1 / row sum of exp2(S)

// ---- helpers --------------------------------------------------------------
__device__ __forceinline__ uint32_t smem_u32(const void* p) {
    uint32_t a;
    asm("{ .reg .u64 t; cvta.to.shared.u64 t, %1; cvt.u32.u64 %0, t; }"
        : "=r"(a) : "l"(p));
    return a;
}
__device__ __forceinline__ uint32_t bf2u(__nv_bfloat162 h) {
    return *reinterpret_cast<uint32_t*>(&h);
}
__device__ __forceinline__ float fexp2(float x) {   // MUFU ex2
    float y; asm("ex2.approx.f32 %0, %1;" : "=f"(y) : "f"(x)); return y;
}

// ---- mma.sync m16n8k16 bf16 (A row-major, B col-major, f32 accum) ---------
__device__ __forceinline__ void mma_acc(float* d, const uint32_t* a,
                                        uint32_t b0, uint32_t b1) {
    asm volatile("mma.sync.aligned.m16n8k16.row.col.f32.bf16.bf16.f32 "
        "{%0,%1,%2,%3}, {%4,%5,%6,%7}, {%8,%9}, {%0,%1,%2,%3};"
        : "+f"(d[0]), "+f"(d[1]), "+f"(d[2]), "+f"(d[3])
        : "r"(a[0]), "r"(a[1]), "r"(a[2]), "r"(a[3]), "r"(b0), "r"(b1));
}
__device__ __forceinline__ void mma_z(float* d, const uint32_t* a,
                                      uint32_t b0, uint32_t b1) {
    asm volatile("mma.sync.aligned.m16n8k16.row.col.f32.bf16.bf16.f32 "
        "{%0,%1,%2,%3}, {%4,%5,%6,%7}, {%8,%9}, {%10,%10,%10,%10};"
        : "=f"(d[0]), "=f"(d[1]), "=f"(d[2]), "=f"(d[3])
        : "r"(a[0]), "r"(a[1]), "r"(a[2]), "r"(a[3]), "r"(b0), "r"(b1),
          "f"(0.0f));
}

// ---- cp.async -------------------------------------------------------------
#define CP16(dst, src) asm volatile("cp.async.cg.shared.global [%0], [%1], 16;" :: "r"(dst), "l"(src))
#define CP8(dst, src)  asm volatile("cp.async.ca.shared.global [%0], [%1], 8;"  :: "r"(dst), "l"(src))
#define CP_COMMIT()    asm volatile("cp.async.commit_group;" ::: "memory")
#define CP_WAIT0()     asm volatile("cp.async.wait_group 0;" ::: "memory")

// ===========================================================================
// Kernel 1: projections via bf16 HMMA. CTA = (b, 128-w tile), 256 threads.
// smem: xT[w][c] bf16 (stride 272B), Wv[c_out][c], Wqk[32][c], qkT[32][w].
// V:  C[c_out][w] = Wv x + bv      (A=Wv, B=xT)
// QK: C[d][w]     = Wqk x + b      (A=Wqk, B=xT), then transpose to [w][d].
// ===========================================================================
#define SPX 272     // row stride bytes for 128-half c rows (256 data + 16 pad)
#define OFX 0
#define OFW 34816
#define OFQ 69632
#define OFT 78336   // qkT [32][272]
// total 87040

__global__ void __launch_bounds__(256) k_proj(
    const float* __restrict__ x,
    const float* __restrict__ Wq, const float* __restrict__ bq,
    const float* __restrict__ Wk, const float* __restrict__ bk,
    const float* __restrict__ Wv, const float* __restrict__ bv)
{
    extern __shared__ __align__(16) char smc[];
    const int b   = blockIdx.y;
    const int w0  = blockIdx.x * 128;
    const int tid = threadIdx.x;
    const int wid = tid >> 5;
    const int lane = tid & 31;
    const int g = lane >> 2, t = lane & 3;

    // ---- Wv -> bf16 smem [c_out][c] ----
    for (int i = tid; i < 128*32; i += 256) {
        int r = i >> 5, cf = i & 31;
        float4 v = *(const float4*)(Wv + r*128 + cf*4);
        uint2 o;
        o.x = bf2u(__floats2bfloat162_rn(v.x, v.y));
        o.y = bf2u(__floats2bfloat162_rn(v.z, v.w));
        *(uint2*)(smc + OFW + r*SPX + cf*8) = o;
    }
    // ---- Wq (rows 0-15) / Wk (rows 16-31) -> bf16 smem ----
    for (int i = tid; i < 32*32; i += 256) {
        int r = i >> 5, cf = i & 31;
        const float* src = (r < 16) ? (Wq + r*128 + cf*4) : (Wk + (r-16)*128 + cf*4);
        float4 v = *(const float4*)src;
        uint2 o;
        o.x = bf2u(__floats2bfloat162_rn(v.x, v.y));
        o.y = bf2u(__floats2bfloat162_rn(v.z, v.w));
        *(uint2*)(smc + OFQ + r*SPX + cf*8) = o;
    }
    // ---- x -> xT[w][c] bf16 (transpose during store) ----
    {
        const int c = tid & 127, hf = tid >> 7;
        const float* xp = x + (size_t)(b*CC + c)*WW + w0 + hf*64;
        #pragma unroll
        for (int it = 0; it < 16; it++) {
            float4 v = *(const float4*)(xp + it*4);
            int w = hf*64 + it*4;
            *(__nv_bfloat16*)(smc + OFX + (w  )*SPX + c*2) = __float2bfloat16(v.x);
            *(__nv_bfloat16*)(smc + OFX + (w+1)*SPX + c*2) = __float2bfloat16(v.y);
            *(__nv_bfloat16*)(smc + OFX + (w+2)*SPX + c*2) = __float2bfloat16(v.z);
            *(__nv_bfloat16*)(smc + OFX + (w+3)*SPX + c*2) = __float2bfloat16(v.w);
        }
    }
    __syncthreads();

    // ---- V GEMM: warp = 16 c_out rows (m-tile), 16 n-tiles, 8 k-tiles ----
    {
        const int mb = wid * 16;
        uint32_t A[8][4];
        #pragma unroll
        for (int kt = 0; kt < 8; kt++) {
            const char* r0 = smc + OFW + (mb + g)*SPX + kt*32 + t*4;
            const char* r1 = smc + OFW + (mb + g + 8)*SPX + kt*32 + t*4;
            A[kt][0] = *(const uint32_t*)r0;
            A[kt][1] = *(const uint32_t*)r1;
            A[kt][2] = *(const uint32_t*)(r0 + 16);
            A[kt][3] = *(const uint32_t*)(r1 + 16);
        }
        const float bias0 = bv[mb + g], bias1 = bv[mb + g + 8];
        #pragma unroll
        for (int nt = 0; nt < 16; nt++) {
            float acc[4] = {bias0, bias0, bias1, bias1};
            #pragma unroll
            for (int kt = 0; kt < 8; kt++) {
                const char* bp = smc + OFX + (nt*8 + g)*SPX + kt*32 + t*4;
                uint32_t b0 = *(const uint32_t*)bp;
                uint32_t b1 = *(const uint32_t*)(bp + 16);
                mma_acc(acc, A[kt], b0, b1);
            }
            const int wcol = w0 + nt*8 + 2*t;
            *(uint32_t*)(g_v + (size_t)(b*CC + mb + g)*WW + wcol) =
                bf2u(__floats2bfloat162_rn(acc[0], acc[1]));
            *(uint32_t*)(g_v + (size_t)(b*CC + mb + g + 8)*WW + wcol) =
                bf2u(__floats2bfloat162_rn(acc[2], acc[3]));
        }
    }

    // ---- QK GEMM: warp -> m-tile (wid&1), n-tiles [(wid>>1)*4, +4) ----
    {
        const int mt = wid & 1, ntb = (wid >> 1) * 4;
        uint32_t A[8][4];
        #pragma unroll
        for (int kt = 0; kt < 8; kt++) {
            const char* r0 = smc + OFQ + (mt*16 + g)*SPX + kt*32 + t*4;
            const char* r1 = smc + OFQ + (mt*16 + g + 8)*SPX + kt*32 + t*4;
            A[kt][0] = *(const uint32_t*)r0;
            A[kt][1] = *(const uint32_t*)r1;
            A[kt][2] = *(const uint32_t*)(r0 + 16);
            A[kt][3] = *(const uint32_t*)(r1 + 16);
        }
        const float* bias = mt ? bk : bq;
        const float bias0 = bias[g], bias1 = bias[g + 8];
        const float psc = mt ? 1.0f : QSCALE;
        #pragma unroll
        for (int nt = ntb; nt < ntb + 4; nt++) {
            float acc[4] = {bias0, bias0, bias1, bias1};
            #pragma unroll
            for (int kt = 0; kt < 8; kt++) {
                const char* bp = smc + OFX + (nt*8 + g)*SPX + kt*32 + t*4;
                uint32_t b0 = *(const uint32_t*)bp;
                uint32_t b1 = *(const uint32_t*)(bp + 16);
                mma_acc(acc, A[kt], b0, b1);
            }
            const int wcol = nt*8 + 2*t;
            *(uint32_t*)(smc + OFT + (mt*16 + g)*SPX + wcol*2) =
                bf2u(__floats2bfloat162_rn(acc[0]*psc, acc[1]*psc));
            *(uint32_t*)(smc + OFT + (mt*16 + g + 8)*SPX + wcol*2) =
                bf2u(__floats2bfloat162_rn(acc[2]*psc, acc[3]*psc));
        }
    }
    __syncthreads();

    // ---- transpose qkT[32][w] -> g_q/g_k [w][16] ----
    {
        const int w = tid & 127, half = tid >> 7;   // half 0 -> q, 1 -> k
        uint32_t u[8];
        #pragma unroll
        for (int i = 0; i < 8; i++) {
            uint32_t lo = *(const uint16_t*)(smc + OFT + (half*16 + 2*i    )*SPX + w*2);
            uint32_t hi = *(const uint16_t*)(smc + OFT + (half*16 + 2*i + 1)*SPX + w*2);
            u[i] = lo | (hi << 16);
        }
        __nv_bfloat16* op = (half ? g_k : g_q) + (size_t)(b*WW + w0 + w)*DD;
        *(uint4*)op       = make_uint4(u[0], u[1], u[2], u[3]);
        *(uint4*)(op + 8) = make_uint4(u[4], u[5], u[6], u[7]);
    }
}

// ===========================================================================
// Kernel 2: row sums l_j = sum_w exp2(S[j,w]);  g_linv = 1/l.
// ===========================================================================
#define SKD 48
__global__ void __launch_bounds__(256, 2) k_stats()
{
    __shared__ __align__(16) char smc[3*128*SKD];
    const uint32_t smb = smem_u32(smc);
    const int tid = threadIdx.x;
    const int wid = tid >> 5;
    const int lane = tid & 31;
    const int g = lane >> 2, t = lane & 3;
    const int b = blockIdx.y, j0 = blockIdx.x * 128;
    const uint32_t QS = smb, KS = smb + 128*SKD;

    {
        int r = tid >> 1, h = tid & 1;
        CP16(QS + r*SKD + h*16, (const char*)(g_q + (size_t)(b*WW + j0 + r)*DD) + h*16);
    }
    {
        int r = tid >> 1, h = tid & 1;
        CP16(KS + r*SKD + h*16, (const char*)(g_k + (size_t)(b*WW + r)*DD) + h*16);
    }
    CP_COMMIT(); CP_WAIT0();
    __syncthreads();

    uint32_t a[4];
    {
        const char* r0 = smc + (wid*16 + g)*SKD + t*4;
        const char* r1 = smc + (wid*16 + g + 8)*SKD + t*4;
        a[0] = *(const uint32_t*)r0;
        a[1] = *(const uint32_t*)r1;
        a[2] = *(const uint32_t*)(r0 + 16);
        a[3] = *(const uint32_t*)(r1 + 16);
    }

    float l0 = 0.0f, l1 = 0.0f;
    for (int wt = 0; wt < 32; wt++) {
        const char* kb = smc + 128*SKD + (wt & 1)*(128*SKD);
        if (wt + 1 < 32) {
            int r = tid >> 1, h = tid & 1;
            CP16(KS + ((wt + 1) & 1)*(128*SKD) + r*SKD + h*16,
                 (const char*)(g_k + (size_t)(b*WW + (wt + 1)*128 + r)*DD) + h*16);
        }
        CP_COMMIT();
        #pragma unroll
        for (int nt = 0; nt < 16; nt++) {
            const char* baddr = kb + (nt*8 + g)*SKD + t*4;
            uint32_t b0 = *(const uint32_t*)baddr;
            uint32_t b1 = *(const uint32_t*)(baddr + 16);
            float d[4];
            mma_z(d, a, b0, b1);
            l0 += fexp2(d[0]) + fexp2(d[1]);
            l1 += fexp2(d[2]) + fexp2(d[3]);
        }
        CP_WAIT0();
        __syncthreads();
    }
    #pragma unroll
    for (int off = 1; off < 4; off <<= 1) {
        l0 += __shfl_down_sync(0xffffffffu, l0, off, 4);
        l1 += __shfl_down_sync(0xffffffffu, l1, off, 4);
    }
    if (t == 0) {
        g_linv[b*WW + j0 + wid*16 + g]     = 1.0f / l0;
        g_linv[b*WW + j0 + wid*16 + g + 8] = 1.0f / l1;
    }
}

// ===========================================================================
// Kernel 3: context + residual (unchanged from R5).
// ===========================================================================
#define SPJ 144
#define OF_KS 0
#define OF_QS 6144
#define OF_VS 12288
#define OF_PT 49152
#define OF_LV 67584

__global__ void __launch_bounds__(256, 2) k_ctx(const float* __restrict__ x,
                                                float* __restrict__ out)
{
    extern __shared__ __align__(16) char smc[];
    const uint32_t smb = smem_u32(smc);
    const int tid = threadIdx.x;
    const int wid = tid >> 5;
    const int lane = tid & 31;
    const int g = lane >> 2, t = lane & 3;
    const int b = blockIdx.y, w0 = blockIdx.x * 128;

    {
        int r = tid >> 1, h = tid & 1;
        CP16(smb + OF_KS + r*SKD + h*16,
             (const char*)(g_k + (size_t)(b*WW + w0 + r)*DD) + h*16);
    }
    #pragma unroll
    for (int i = 0; i < 4; i++) {
        int idx = tid + i*256;
        CP16(smb + OF_LV + idx*16, (const char*)(g_linv + b*WW) + idx*16);
    }
    {
        int r = tid >> 2, h = tid & 3;
        CP8(smb + OF_QS + r*SKD + h*8,
            (const char*)(g_q + (size_t)(b*WW + r)*DD) + h*8);
    }
    #pragma unroll
    for (int i = 0; i < 4; i++) {
        int cid = tid + i*256;
        int c = cid >> 3, ch = cid & 7;
        CP16(smb + OF_VS + c*SPJ + ch*16,
             (const char*)(g_v + (size_t)(b*CC + c)*WW) + ch*16);
    }
    CP_COMMIT(); CP_WAIT0();
    __syncthreads();

    uint32_t ak[4];
    {
        const char* r0 = smc + OF_KS + (wid*16 + g)*SKD + t*4;
        const char* r1 = smc + OF_KS + (wid*16 + g + 8)*SKD + t*4;
        ak[0] = *(const uint32_t*)r0;
        ak[1] = *(const uint32_t*)r1;
        ak[2] = *(const uint32_t*)(r0 + 16);
        ak[3] = *(const uint32_t*)(r1 + 16);
    }

    const int c0w = (wid & 3) * 32;
    const int wc0 = (wid >> 2) * 64;
    float acc[2][8][4];
    #pragma unroll
    for (int mt = 0; mt < 2; mt++)
        #pragma unroll
        for (int nt = 0; nt < 8; nt++)
            #pragma unroll
            for (int e = 0; e < 4; e++) acc[mt][nt][e] = 0.0f;

    for (int jt = 0; jt < 64; jt++) {
        const int buf = jt & 1;
        const int j0 = jt * 64;

        if (jt + 1 < 64) {
            const int jn = j0 + 64, nb = buf ^ 1;
            int r = tid >> 2, h = tid & 3;
            CP8(smb + OF_QS + nb*3072 + r*SKD + h*8,
                (const char*)(g_q + (size_t)(b*WW + jn + r)*DD) + h*8);
            #pragma unroll
            for (int i = 0; i < 4; i++) {
                int cid = tid + i*256;
                int c = cid >> 3, ch = cid & 7;
                CP16(smb + OF_VS + nb*18432 + c*SPJ + ch*16,
                     (const char*)(g_v + (size_t)(b*CC + c)*WW + jn) + ch*16);
            }
        }
        CP_COMMIT();

        const char* qb = smc + OF_QS + buf*3072;
        const float* lv = (const float*)(smc + OF_LV) + j0;
        #pragma unroll
        for (int nt = 0; nt < 8; nt++) {
            const char* baddr = qb + (nt*8 + g)*SKD + t*4;
            uint32_t b0 = *(const uint32_t*)baddr;
            uint32_t b1 = *(const uint32_t*)(baddr + 16);
            float d[4];
            mma_z(d, ak, b0, b1);
            float2 l01 = *(const float2*)(lv + nt*8 + 2*t);
            float p0 = fexp2(d[0]) * l01.x;
            float p1 = fexp2(d[1]) * l01.y;
            float p2 = fexp2(d[2]) * l01.x;
            float p3 = fexp2(d[3]) * l01.y;
            *(uint32_t*)(smc + OF_PT + (wid*16 + g)*SPJ     + (nt*8 + 2*t)*2) =
                bf2u(__floats2bfloat162_rn(p0, p1));
            *(uint32_t*)(smc + OF_PT + (wid*16 + g + 8)*SPJ + (nt*8 + 2*t)*2) =
                bf2u(__floats2bfloat162_rn(p2, p3));
        }
        __syncthreads();

        #pragma unroll
        for (int k0 = 0; k0 < 4; k0++) {
            uint32_t av[2][4];
            #pragma unroll
            for (int mt = 0; mt < 2; mt++) {
                const char* r0 = smc + OF_VS + buf*18432
                               + (c0w + mt*16 + g)*SPJ + k0*32 + t*4;
                const char* r1 = r0 + 8*SPJ;
                av[mt][0] = *(const uint32_t*)r0;
                av[mt][1] = *(const uint32_t*)r1;
                av[mt][2] = *(const uint32_t*)(r0 + 16);
                av[mt][3] = *(const uint32_t*)(r1 + 16);
            }
            #pragma unroll
            for (int nt = 0; nt < 8; nt++) {
                const char* pb = smc + OF_PT + (wc0 + nt*8 + g)*SPJ + k0*32 + t*4;
                uint32_t b0 = *(const uint32_t*)pb;
                uint32_t b1 = *(const uint32_t*)(pb + 16);
                mma_acc(acc[0][nt], av[0], b0, b1);
                mma_acc(acc[1][nt], av[1], b0, b1);
            }
        }
        CP_WAIT0();
        __syncthreads();
    }

    #pragma unroll
    for (int mt = 0; mt < 2; mt++) {
        #pragma unroll
        for (int nt = 0; nt < 8; nt++) {
            int c  = c0w + mt*16 + g;
            int wc = w0 + wc0 + nt*8 + 2*t;
            size_t i0 = (size_t)(b*CC + c)*WW + wc;
            size_t i1 = i0 + 8*WW;
            float2 x0 = *(const float2*)(x + i0);
            float2 x1 = *(const float2*)(x + i1);
            *(float2*)(out + i0) = make_float2(acc[mt][nt][0] + x0.x,
                                               acc[mt][nt][1] + x0.y);
            *(float2*)(out + i1) = make_float2(acc[mt][nt][2] + x1.x,
                                               acc[mt][nt][3] + x1.y);
        }
    }
}

// ===========================================================================
extern "C" void kernel_launch(void* const* d_in, const int* in_sizes, int n_in,
                              void* d_out, int out_size)
{
    const float* x  = (const float*)d_in[0];
    const float* Wq = (const float*)d_in[1];
    const float* bq = (const float*)d_in[2];
    const float* Wk = (const float*)d_in[3];
    const float* bk = (const float*)d_in[4];
    const float* Wv = (const float*)d_in[5];
    const float* bv = (const float*)d_in[6];
    float* out = (float*)d_out;

    const int smem_proj = 87040;
    const int smem_ctx  = 83968;
    cudaFuncSetAttribute(k_proj, cudaFuncAttributeMaxDynamicSharedMemorySize, smem_proj);
    cudaFuncSetAttribute(k_ctx,  cudaFuncAttributeMaxDynamicSharedMemorySize, smem_ctx);

    dim3 g(WW/128, BB);
    k_proj <<<g, 256, smem_proj>>>(x, Wq, bq, Wk, bk, Wv, bv);
    k_stats<<<g, 256>>>();
    k_ctx  <<<g, 256, smem_ctx>>>(x, out);
}

// round 7
// speedup vs baseline: 15.0872x; 1.4830x over previous
#include <cuda_runtime.h>
#include <cuda_bf16.h>
#include <cstdint>

#define BB 8
#define CC 128
#define WW 4096
#define DD 16

// 0.25 (= D^-0.5) * log2(e): folded into q so softmax uses exp2 directly.
#define QSCALE 0.3606737602222409f

typedef unsigned long long ull;

// ---- scratch (__device__ globals; no allocs allowed) ----------------------
__device__ __nv_bfloat16 g_q[(size_t)BB*WW*DD];   // [b][w][d], pre-scaled
__device__ __nv_bfloat16 g_k[(size_t)BB*WW*DD];   // [b][w][d]
__device__ __nv_bfloat16 g_v[(size_t)BB*CC*WW];   // [b][c][w]
__device__ float g_linv[BB*WW];                    // 1 / row sum of exp2(S)

// ---- helpers --------------------------------------------------------------
__device__ __forceinline__ uint32_t smem_u32(const void* p) {
    uint32_t a;
    asm("{ .reg .u64 t; cvta.to.shared.u64 t, %1; cvt.u32.u64 %0, t; }"
        : "=r"(a) : "l"(p));
    return a;
}
__device__ __forceinline__ uint32_t bf2u(__nv_bfloat162 h) {
    return *reinterpret_cast<uint32_t*>(&h);
}
__device__ __forceinline__ float fexp2(float x) {   // MUFU ex2
    float y; asm("ex2.approx.f32 %0, %1;" : "=f"(y) : "f"(x)); return y;
}

// ---- mma.sync m16n8k16 bf16 (A row-major, B col-major, f32 accum) ---------
__device__ __forceinline__ void mma_acc(float* d, const uint32_t* a,
                                        uint32_t b0, uint32_t b1) {
    asm volatile("mma.sync.aligned.m16n8k16.row.col.f32.bf16.bf16.f32 "
        "{%0,%1,%2,%3}, {%4,%5,%6,%7}, {%8,%9}, {%0,%1,%2,%3};"
        : "+f"(d[0]), "+f"(d[1]), "+f"(d[2]), "+f"(d[3])
        : "r"(a[0]), "r"(a[1]), "r"(a[2]), "r"(a[3]), "r"(b0), "r"(b1));
}
__device__ __forceinline__ void mma_z(float* d, const uint32_t* a,
                                      uint32_t b0, uint32_t b1) {
    asm volatile("mma.sync.aligned.m16n8k16.row.col.f32.bf16.bf16.f32 "
        "{%0,%1,%2,%3}, {%4,%5,%6,%7}, {%8,%9}, {%10,%10,%10,%10};"
        : "=f"(d[0]), "=f"(d[1]), "=f"(d[2]), "=f"(d[3])
        : "r"(a[0]), "r"(a[1]), "r"(a[2]), "r"(a[3]), "r"(b0), "r"(b1),
          "f"(0.0f));
}

// ---- cp.async -------------------------------------------------------------
#define CP16(dst, src) asm volatile("cp.async.cg.shared.global [%0], [%1], 16;" :: "r"(dst), "l"(src))
#define CP8(dst, src)  asm volatile("cp.async.ca.shared.global [%0], [%1], 8;"  :: "r"(dst), "l"(src))
#define CP_COMMIT()    asm volatile("cp.async.commit_group;" ::: "memory")
#define CP_WAIT0()     asm volatile("cp.async.wait_group 0;" ::: "memory")

// ===========================================================================
// Kernel 1: projections via bf16 HMMA (unchanged from R6).
// ===========================================================================
#define SPX 272
#define OFX 0
#define OFW 34816
#define OFQ 69632
#define OFT 78336

__global__ void __launch_bounds__(256) k_proj(
    const float* __restrict__ x,
    const float* __restrict__ Wq, const float* __restrict__ bq,
    const float* __restrict__ Wk, const float* __restrict__ bk,
    const float* __restrict__ Wv, const float* __restrict__ bv)
{
    extern __shared__ __align__(16) char smc[];
    const int b   = blockIdx.y;
    const int w0  = blockIdx.x * 128;
    const int tid = threadIdx.x;
    const int wid = tid >> 5;
    const int lane = tid & 31;
    const int g = lane >> 2, t = lane & 3;

    for (int i = tid; i < 128*32; i += 256) {
        int r = i >> 5, cf = i & 31;
        float4 v = *(const float4*)(Wv + r*128 + cf*4);
        uint2 o;
        o.x = bf2u(__floats2bfloat162_rn(v.x, v.y));
        o.y = bf2u(__floats2bfloat162_rn(v.z, v.w));
        *(uint2*)(smc + OFW + r*SPX + cf*8) = o;
    }
    for (int i = tid; i < 32*32; i += 256) {
        int r = i >> 5, cf = i & 31;
        const float* src = (r < 16) ? (Wq + r*128 + cf*4) : (Wk + (r-16)*128 + cf*4);
        float4 v = *(const float4*)src;
        uint2 o;
        o.x = bf2u(__floats2bfloat162_rn(v.x, v.y));
        o.y = bf2u(__floats2bfloat162_rn(v.z, v.w));
        *(uint2*)(smc + OFQ + r*SPX + cf*8) = o;
    }
    {
        const int c = tid & 127, hf = tid >> 7;
        const float* xp = x + (size_t)(b*CC + c)*WW + w0 + hf*64;
        #pragma unroll
        for (int it = 0; it < 16; it++) {
            float4 v = *(const float4*)(xp + it*4);
            int w = hf*64 + it*4;
            *(__nv_bfloat16*)(smc + OFX + (w  )*SPX + c*2) = __float2bfloat16(v.x);
            *(__nv_bfloat16*)(smc + OFX + (w+1)*SPX + c*2) = __float2bfloat16(v.y);
            *(__nv_bfloat16*)(smc + OFX + (w+2)*SPX + c*2) = __float2bfloat16(v.z);
            *(__nv_bfloat16*)(smc + OFX + (w+3)*SPX + c*2) = __float2bfloat16(v.w);
        }
    }
    __syncthreads();

    {   // V GEMM
        const int mb = wid * 16;
        uint32_t A[8][4];
        #pragma unroll
        for (int kt = 0; kt < 8; kt++) {
            const char* r0 = smc + OFW + (mb + g)*SPX + kt*32 + t*4;
            const char* r1 = smc + OFW + (mb + g + 8)*SPX + kt*32 + t*4;
            A[kt][0] = *(const uint32_t*)r0;
            A[kt][1] = *(const uint32_t*)r1;
            A[kt][2] = *(const uint32_t*)(r0 + 16);
            A[kt][3] = *(const uint32_t*)(r1 + 16);
        }
        const float bias0 = bv[mb + g], bias1 = bv[mb + g + 8];
        #pragma unroll
        for (int nt = 0; nt < 16; nt++) {
            float acc[4] = {bias0, bias0, bias1, bias1};
            #pragma unroll
            for (int kt = 0; kt < 8; kt++) {
                const char* bp = smc + OFX + (nt*8 + g)*SPX + kt*32 + t*4;
                uint32_t b0 = *(const uint32_t*)bp;
                uint32_t b1 = *(const uint32_t*)(bp + 16);
                mma_acc(acc, A[kt], b0, b1);
            }
            const int wcol = w0 + nt*8 + 2*t;
            *(uint32_t*)(g_v + (size_t)(b*CC + mb + g)*WW + wcol) =
                bf2u(__floats2bfloat162_rn(acc[0], acc[1]));
            *(uint32_t*)(g_v + (size_t)(b*CC + mb + g + 8)*WW + wcol) =
                bf2u(__floats2bfloat162_rn(acc[2], acc[3]));
        }
    }

    {   // QK GEMM
        const int mt = wid & 1, ntb = (wid >> 1) * 4;
        uint32_t A[8][4];
        #pragma unroll
        for (int kt = 0; kt < 8; kt++) {
            const char* r0 = smc + OFQ + (mt*16 + g)*SPX + kt*32 + t*4;
            const char* r1 = smc + OFQ + (mt*16 + g + 8)*SPX + kt*32 + t*4;
            A[kt][0] = *(const uint32_t*)r0;
            A[kt][1] = *(const uint32_t*)r1;
            A[kt][2] = *(const uint32_t*)(r0 + 16);
            A[kt][3] = *(const uint32_t*)(r1 + 16);
        }
        const float* bias = mt ? bk : bq;
        const float bias0 = bias[g], bias1 = bias[g + 8];
        const float psc = mt ? 1.0f : QSCALE;
        #pragma unroll
        for (int nt = ntb; nt < ntb + 4; nt++) {
            float acc[4] = {bias0, bias0, bias1, bias1};
            #pragma unroll
            for (int kt = 0; kt < 8; kt++) {
                const char* bp = smc + OFX + (nt*8 + g)*SPX + kt*32 + t*4;
                uint32_t b0 = *(const uint32_t*)bp;
                uint32_t b1 = *(const uint32_t*)(bp + 16);
                mma_acc(acc, A[kt], b0, b1);
            }
            const int wcol = nt*8 + 2*t;
            *(uint32_t*)(smc + OFT + (mt*16 + g)*SPX + wcol*2) =
                bf2u(__floats2bfloat162_rn(acc[0]*psc, acc[1]*psc));
            *(uint32_t*)(smc + OFT + (mt*16 + g + 8)*SPX + wcol*2) =
                bf2u(__floats2bfloat162_rn(acc[2]*psc, acc[3]*psc));
        }
    }
    __syncthreads();

    {   // transpose qkT -> g_q/g_k [w][16]
        const int w = tid & 127, half = tid >> 7;
        uint32_t u[8];
        #pragma unroll
        for (int i = 0; i < 8; i++) {
            uint32_t lo = *(const uint16_t*)(smc + OFT + (half*16 + 2*i    )*SPX + w*2);
            uint32_t hi = *(const uint16_t*)(smc + OFT + (half*16 + 2*i + 1)*SPX + w*2);
            u[i] = lo | (hi << 16);
        }
        __nv_bfloat16* op = (half ? g_k : g_q) + (size_t)(b*WW + w0 + w)*DD;
        *(uint4*)op       = make_uint4(u[0], u[1], u[2], u[3]);
        *(uint4*)(op + 8) = make_uint4(u[4], u[5], u[6], u[7]);
    }
}

// ===========================================================================
// Kernel 2: row sums (unchanged from R6).
// ===========================================================================
#define SKD 48
__global__ void __launch_bounds__(256, 2) k_stats()
{
    __shared__ __align__(16) char smc[3*128*SKD];
    const uint32_t smb = smem_u32(smc);
    const int tid = threadIdx.x;
    const int wid = tid >> 5;
    const int lane = tid & 31;
    const int g = lane >> 2, t = lane & 3;
    const int b = blockIdx.y, j0 = blockIdx.x * 128;
    const uint32_t QS = smb, KS = smb + 128*SKD;

    {
        int r = tid >> 1, h = tid & 1;
        CP16(QS + r*SKD + h*16, (const char*)(g_q + (size_t)(b*WW + j0 + r)*DD) + h*16);
    }
    {
        int r = tid >> 1, h = tid & 1;
        CP16(KS + r*SKD + h*16, (const char*)(g_k + (size_t)(b*WW + r)*DD) + h*16);
    }
    CP_COMMIT(); CP_WAIT0();
    __syncthreads();

    uint32_t a[4];
    {
        const char* r0 = smc + (wid*16 + g)*SKD + t*4;
        const char* r1 = smc + (wid*16 + g + 8)*SKD + t*4;
        a[0] = *(const uint32_t*)r0;
        a[1] = *(const uint32_t*)r1;
        a[2] = *(const uint32_t*)(r0 + 16);
        a[3] = *(const uint32_t*)(r1 + 16);
    }

    float l0 = 0.0f, l1 = 0.0f;
    for (int wt = 0; wt < 32; wt++) {
        const char* kb = smc + 128*SKD + (wt & 1)*(128*SKD);
        if (wt + 1 < 32) {
            int r = tid >> 1, h = tid & 1;
            CP16(KS + ((wt + 1) & 1)*(128*SKD) + r*SKD + h*16,
                 (const char*)(g_k + (size_t)(b*WW + (wt + 1)*128 + r)*DD) + h*16);
        }
        CP_COMMIT();
        #pragma unroll
        for (int nt = 0; nt < 16; nt++) {
            const char* baddr = kb + (nt*8 + g)*SKD + t*4;
            uint32_t b0 = *(const uint32_t*)baddr;
            uint32_t b1 = *(const uint32_t*)(baddr + 16);
            float d[4];
            mma_z(d, a, b0, b1);
            l0 += fexp2(d[0]) + fexp2(d[1]);
            l1 += fexp2(d[2]) + fexp2(d[3]);
        }
        CP_WAIT0();
        __syncthreads();
    }
    #pragma unroll
    for (int off = 1; off < 4; off <<= 1) {
        l0 += __shfl_down_sync(0xffffffffu, l0, off, 4);
        l1 += __shfl_down_sync(0xffffffffu, l1, off, 4);
    }
    if (t == 0) {
        g_linv[b*WW + j0 + wid*16 + g]     = 1.0f / l0;
        g_linv[b*WW + j0 + wid*16 + g + 8] = 1.0f / l1;
    }
}

// ===========================================================================
// Kernel 3: context + residual, SOFTWARE-PIPELINED.
// Iter jt: QK(jt+1) -> Pt[(jt+1)&1]  AND  PV(jt) <- Pt[jt&1], ONE sync/iter.
// Warps skew across phases -> MUFU epilogue overlaps HMMA.
// smem: ks@0 (6144), qring@6144 (4x3072), vs@18432 (2x18432),
//       Pt@55296 (2x18432). total 92160. linv via __ldg (L1).
// ===========================================================================
#define SPJ 144
#define OF_KS 0
#define OF_QR 6144
#define OF_VS 18432
#define OF_PT 55296

__global__ void __launch_bounds__(256, 2) k_ctx(const float* __restrict__ x,
                                                float* __restrict__ out)
{
    extern __shared__ __align__(16) char smc[];
    const uint32_t smb = smem_u32(smc);
    const int tid = threadIdx.x;
    const int wid = tid >> 5;
    const int lane = tid & 31;
    const int g = lane >> 2, t = lane & 3;
    const int b = blockIdx.y, w0 = blockIdx.x * 128;

    // ---- preamble: ks (fixed), q tile 0 ----
    {
        int r = tid >> 1, h = tid & 1;
        CP16(smb + OF_KS + r*SKD + h*16,
             (const char*)(g_k + (size_t)(b*WW + w0 + r)*DD) + h*16);
    }
    {
        int r = tid >> 2, h = tid & 3;
        CP8(smb + OF_QR + r*SKD + h*8,
            (const char*)(g_q + (size_t)(b*WW + r)*DD) + h*8);
    }
    CP_COMMIT(); CP_WAIT0();
    __syncthreads();

    // A fragments for QK (k rows = warp's 16 w rows), fixed
    uint32_t ak[4];
    {
        const char* r0 = smc + OF_KS + (wid*16 + g)*SKD + t*4;
        const char* r1 = smc + OF_KS + (wid*16 + g + 8)*SKD + t*4;
        ak[0] = *(const uint32_t*)r0;
        ak[1] = *(const uint32_t*)r1;
        ak[2] = *(const uint32_t*)(r0 + 16);
        ak[3] = *(const uint32_t*)(r1 + 16);
    }

    const int c0w = (wid & 3) * 32;
    const int wc0 = (wid >> 2) * 64;
    float acc[2][8][4];
    #pragma unroll
    for (int mt = 0; mt < 2; mt++)
        #pragma unroll
        for (int nt = 0; nt < 8; nt++)
            #pragma unroll
            for (int e = 0; e < 4; e++) acc[mt][nt][e] = 0.0f;

    const float* lvg = g_linv + b*WW;

    for (int jt = -1; jt < 64; jt++) {
        // ---- prefetch: q(jt+2) -> qring[(jt+2)&3], v(jt+1) -> vs[(jt+1)&1]
        if (jt + 2 < 64) {
            int r = tid >> 2, h = tid & 3;
            CP8(smb + OF_QR + ((jt + 2) & 3)*3072 + r*SKD + h*8,
                (const char*)(g_q + (size_t)(b*WW + (jt + 2)*64 + r)*DD) + h*8);
        }
        if (jt + 1 < 64) {
            #pragma unroll
            for (int i = 0; i < 4; i++) {
                int cid = tid + i*256;
                int c = cid >> 3, ch = cid & 7;
                CP16(smb + OF_VS + ((jt + 1) & 1)*18432 + c*SPJ + ch*16,
                     (const char*)(g_v + (size_t)(b*CC + c)*WW + (jt + 1)*64) + ch*16);
            }
        }
        CP_COMMIT();

        // ---- QK(jt+1) -> Pt[(jt+1)&1] ----
        if (jt + 1 < 64) {
            const int jn = (jt + 1) * 64;
            const char* qb = smc + OF_QR + ((jt + 1) & 3)*3072;
            char* ptb = smc + OF_PT + ((jt + 1) & 1)*18432;
            #pragma unroll
            for (int nt = 0; nt < 8; nt++) {
                const char* baddr = qb + (nt*8 + g)*SKD + t*4;
                uint32_t b0 = *(const uint32_t*)baddr;
                uint32_t b1 = *(const uint32_t*)(baddr + 16);
                float d[4];
                mma_z(d, ak, b0, b1);
                float2 l01 = __ldg((const float2*)(lvg + jn + nt*8 + 2*t));
                float p0 = fexp2(d[0]) * l01.x;
                float p1 = fexp2(d[1]) * l01.y;
                float p2 = fexp2(d[2]) * l01.x;
                float p3 = fexp2(d[3]) * l01.y;
                *(uint32_t*)(ptb + (wid*16 + g)*SPJ     + (nt*8 + 2*t)*2) =
                    bf2u(__floats2bfloat162_rn(p0, p1));
                *(uint32_t*)(ptb + (wid*16 + g + 8)*SPJ + (nt*8 + 2*t)*2) =
                    bf2u(__floats2bfloat162_rn(p2, p3));
            }
        }

        // ---- PV(jt) <- Pt[jt&1], vs[jt&1] ----
        if (jt >= 0) {
            const char* vb = smc + OF_VS + (jt & 1)*18432;
            const char* pt = smc + OF_PT + (jt & 1)*18432;
            #pragma unroll
            for (int k0 = 0; k0 < 4; k0++) {
                uint32_t av[2][4];
                #pragma unroll
                for (int mt = 0; mt < 2; mt++) {
                    const char* r0 = vb + (c0w + mt*16 + g)*SPJ + k0*32 + t*4;
                    const char* r1 = r0 + 8*SPJ;
                    av[mt][0] = *(const uint32_t*)r0;
                    av[mt][1] = *(const uint32_t*)r1;
                    av[mt][2] = *(const uint32_t*)(r0 + 16);
                    av[mt][3] = *(const uint32_t*)(r1 + 16);
                }
                #pragma unroll
                for (int nt = 0; nt < 8; nt++) {
                    const char* pb = pt + (wc0 + nt*8 + g)*SPJ + k0*32 + t*4;
                    uint32_t b0 = *(const uint32_t*)pb;
                    uint32_t b1 = *(const uint32_t*)(pb + 16);
                    mma_acc(acc[0][nt], av[0], b0, b1);
                    mma_acc(acc[1][nt], av[1], b0, b1);
                }
            }
        }

        CP_WAIT0();
        __syncthreads();
    }

    // ---- epilogue: out = acc + x ----
    #pragma unroll
    for (int mt = 0; mt < 2; mt++) {
        #pragma unroll
        for (int nt = 0; nt < 8; nt++) {
            int c  = c0w + mt*16 + g;
            int wc = w0 + wc0 + nt*8 + 2*t;
            size_t i0 = (size_t)(b*CC + c)*WW + wc;
            size_t i1 = i0 + 8*WW;
            float2 x0 = *(const float2*)(x + i0);
            float2 x1 = *(const float2*)(x + i1);
            *(float2*)(out + i0) = make_float2(acc[mt][nt][0] + x0.x,
                                               acc[mt][nt][1] + x0.y);
            *(float2*)(out + i1) = make_float2(acc[mt][nt][2] + x1.x,
                                               acc[mt][nt][3] + x1.y);
        }
    }
}

// ===========================================================================
extern "C" void kernel_launch(void* const* d_in, const int* in_sizes, int n_in,
                              void* d_out, int out_size)
{
    const float* x  = (const float*)d_in[0];
    const float* Wq = (const float*)d_in[1];
    const float* bq = (const float*)d_in[2];
    const float* Wk = (const float*)d_in[3];
    const float* bk = (const float*)d_in[4];
    const float* Wv = (const float*)d_in[5];
    const float* bv = (const float*)d_in[6];
    float* out = (float*)d_out;

    const int smem_proj = 87040;
    const int smem_ctx  = 92160;
    cudaFuncSetAttribute(k_proj, cudaFuncAttributeMaxDynamicSharedMemorySize, smem_proj);
    cudaFuncSetAttribute(k_ctx,  cudaFuncAttributeMaxDynamicSharedMemorySize, smem_ctx);

    dim3 g(WW/128, BB);
    k_proj <<<g, 256, smem_proj>>>(x, Wq, bq, Wk, bk, Wv, bv);
    k_stats<<<g, 256>>>();
    k_ctx  <<<g, 256, smem_ctx>>>(x, out);
}

// round 8
// speedup vs baseline: 16.8730x; 1.1184x over previous
#include <cuda_runtime.h>
#include <cuda_bf16.h>
#include <cstdint>

#define BB 8
#define CC 128
#define WW 4096
#define DD 16

// 0.25 (= D^-0.5) * log2(e): folded into q so softmax uses exp2 directly.
#define QSCALE 0.3606737602222409f

typedef unsigned long long ull;

// ---- scratch (__device__ globals; no allocs allowed) ----------------------
__device__ __nv_bfloat16 g_q[(size_t)BB*WW*DD];   // [b][w][d], pre-scaled
__device__ __nv_bfloat16 g_k[(size_t)BB*WW*DD];   // [b][w][d]
__device__ __nv_bfloat16 g_v[(size_t)BB*CC*WW];   // [b][c][w]; later scaled by linv[j]

// ---- helpers --------------------------------------------------------------
__device__ __forceinline__ uint32_t smem_u32(const void* p) {
    uint32_t a;
    asm("{ .reg .u64 t; cvta.to.shared.u64 t, %1; cvt.u32.u64 %0, t; }"
        : "=r"(a) : "l"(p));
    return a;
}
__device__ __forceinline__ uint32_t bf2u(__nv_bfloat162 h) {
    return *reinterpret_cast<uint32_t*>(&h);
}

// ---- mma.sync m16n8k16 bf16 (A row-major, B col-major, f32 accum) ---------
__device__ __forceinline__ void mma_acc(float* d, const uint32_t* a,
                                        uint32_t b0, uint32_t b1) {
    asm volatile("mma.sync.aligned.m16n8k16.row.col.f32.bf16.bf16.f32 "
        "{%0,%1,%2,%3}, {%4,%5,%6,%7}, {%8,%9}, {%0,%1,%2,%3};"
        : "+f"(d[0]), "+f"(d[1]), "+f"(d[2]), "+f"(d[3])
        : "r"(a[0]), "r"(a[1]), "r"(a[2]), "r"(a[3]), "r"(b0), "r"(b1));
}
__device__ __forceinline__ void mma_z(float* d, const uint32_t* a,
                                      uint32_t b0, uint32_t b1) {
    asm volatile("mma.sync.aligned.m16n8k16.row.col.f32.bf16.bf16.f32 "
        "{%0,%1,%2,%3}, {%4,%5,%6,%7}, {%8,%9}, {%10,%10,%10,%10};"
        : "=f"(d[0]), "=f"(d[1]), "=f"(d[2]), "=f"(d[3])
        : "r"(a[0]), "r"(a[1]), "r"(a[2]), "r"(a[3]), "r"(b0), "r"(b1),
          "f"(0.0f));
}

// ---- cp.async -------------------------------------------------------------
#define CP16(dst, src) asm volatile("cp.async.cg.shared.global [%0], [%1], 16;" :: "r"(dst), "l"(src))
#define CP8(dst, src)  asm volatile("cp.async.ca.shared.global [%0], [%1], 8;"  :: "r"(dst), "l"(src))
#define CP_COMMIT()    asm volatile("cp.async.commit_group;" ::: "memory")
#define CP_WAIT0()     asm volatile("cp.async.wait_group 0;" ::: "memory")

// ===========================================================================
// Kernel 1: projections via bf16 HMMA (unchanged from R6).
// ===========================================================================
#define SPX 272
#define OFX 0
#define OFW 34816
#define OFQ 69632
#define OFT 78336

__global__ void __launch_bounds__(256) k_proj(
    const float* __restrict__ x,
    const float* __restrict__ Wq, const float* __restrict__ bq,
    const float* __restrict__ Wk, const float* __restrict__ bk,
    const float* __restrict__ Wv, const float* __restrict__ bv)
{
    extern __shared__ __align__(16) char smc[];
    const int b   = blockIdx.y;
    const int w0  = blockIdx.x * 128;
    const int tid = threadIdx.x;
    const int wid = tid >> 5;
    const int lane = tid & 31;
    const int g = lane >> 2, t = lane & 3;

    for (int i = tid; i < 128*32; i += 256) {
        int r = i >> 5, cf = i & 31;
        float4 v = *(const float4*)(Wv + r*128 + cf*4);
        uint2 o;
        o.x = bf2u(__floats2bfloat162_rn(v.x, v.y));
        o.y = bf2u(__floats2bfloat162_rn(v.z, v.w));
        *(uint2*)(smc + OFW + r*SPX + cf*8) = o;
    }
    for (int i = tid; i < 32*32; i += 256) {
        int r = i >> 5, cf = i & 31;
        const float* src = (r < 16) ? (Wq + r*128 + cf*4) : (Wk + (r-16)*128 + cf*4);
        float4 v = *(const float4*)src;
        uint2 o;
        o.x = bf2u(__floats2bfloat162_rn(v.x, v.y));
        o.y = bf2u(__floats2bfloat162_rn(v.z, v.w));
        *(uint2*)(smc + OFQ + r*SPX + cf*8) = o;
    }
    {
        const int c = tid & 127, hf = tid >> 7;
        const float* xp = x + (size_t)(b*CC + c)*WW + w0 + hf*64;
        #pragma unroll
        for (int it = 0; it < 16; it++) {
            float4 v = *(const float4*)(xp + it*4);
            int w = hf*64 + it*4;
            *(__nv_bfloat16*)(smc + OFX + (w  )*SPX + c*2) = __float2bfloat16(v.x);
            *(__nv_bfloat16*)(smc + OFX + (w+1)*SPX + c*2) = __float2bfloat16(v.y);
            *(__nv_bfloat16*)(smc + OFX + (w+2)*SPX + c*2) = __float2bfloat16(v.z);
            *(__nv_bfloat16*)(smc + OFX + (w+3)*SPX + c*2) = __float2bfloat16(v.w);
        }
    }
    __syncthreads();

    {   // V GEMM
        const int mb = wid * 16;
        uint32_t A[8][4];
        #pragma unroll
        for (int kt = 0; kt < 8; kt++) {
            const char* r0 = smc + OFW + (mb + g)*SPX + kt*32 + t*4;
            const char* r1 = smc + OFW + (mb + g + 8)*SPX + kt*32 + t*4;
            A[kt][0] = *(const uint32_t*)r0;
            A[kt][1] = *(const uint32_t*)r1;
            A[kt][2] = *(const uint32_t*)(r0 + 16);
            A[kt][3] = *(const uint32_t*)(r1 + 16);
        }
        const float bias0 = bv[mb + g], bias1 = bv[mb + g + 8];
        #pragma unroll
        for (int nt = 0; nt < 16; nt++) {
            float acc[4] = {bias0, bias0, bias1, bias1};
            #pragma unroll
            for (int kt = 0; kt < 8; kt++) {
                const char* bp = smc + OFX + (nt*8 + g)*SPX + kt*32 + t*4;
                uint32_t b0 = *(const uint32_t*)bp;
                uint32_t b1 = *(const uint32_t*)(bp + 16);
                mma_acc(acc, A[kt], b0, b1);
            }
            const int wcol = w0 + nt*8 + 2*t;
            *(uint32_t*)(g_v + (size_t)(b*CC + mb + g)*WW + wcol) =
                bf2u(__floats2bfloat162_rn(acc[0], acc[1]));
            *(uint32_t*)(g_v + (size_t)(b*CC + mb + g + 8)*WW + wcol) =
                bf2u(__floats2bfloat162_rn(acc[2], acc[3]));
        }
    }

    {   // QK GEMM
        const int mt = wid & 1, ntb = (wid >> 1) * 4;
        uint32_t A[8][4];
        #pragma unroll
        for (int kt = 0; kt < 8; kt++) {
            const char* r0 = smc + OFQ + (mt*16 + g)*SPX + kt*32 + t*4;
            const char* r1 = smc + OFQ + (mt*16 + g + 8)*SPX + kt*32 + t*4;
            A[kt][0] = *(const uint32_t*)r0;
            A[kt][1] = *(const uint32_t*)r1;
            A[kt][2] = *(const uint32_t*)(r0 + 16);
            A[kt][3] = *(const uint32_t*)(r1 + 16);
        }
        const float* bias = mt ? bk : bq;
        const float bias0 = bias[g], bias1 = bias[g + 8];
        const float psc = mt ? 1.0f : QSCALE;
        #pragma unroll
        for (int nt = ntb; nt < ntb + 4; nt++) {
            float acc[4] = {bias0, bias0, bias1, bias1};
            #pragma unroll
            for (int kt = 0; kt < 8; kt++) {
                const char* bp = smc + OFX + (nt*8 + g)*SPX + kt*32 + t*4;
                uint32_t b0 = *(const uint32_t*)bp;
                uint32_t b1 = *(const uint32_t*)(bp + 16);
                mma_acc(acc, A[kt], b0, b1);
            }
            const int wcol = nt*8 + 2*t;
            *(uint32_t*)(smc + OFT + (mt*16 + g)*SPX + wcol*2) =
                bf2u(__floats2bfloat162_rn(acc[0]*psc, acc[1]*psc));
            *(uint32_t*)(smc + OFT + (mt*16 + g + 8)*SPX + wcol*2) =
                bf2u(__floats2bfloat162_rn(acc[2]*psc, acc[3]*psc));
        }
    }
    __syncthreads();

    {   // transpose qkT -> g_q/g_k [w][16]
        const int w = tid & 127, half = tid >> 7;
        uint32_t u[8];
        #pragma unroll
        for (int i = 0; i < 8; i++) {
            uint32_t lo = *(const uint16_t*)(smc + OFT + (half*16 + 2*i    )*SPX + w*2);
            uint32_t hi = *(const uint16_t*)(smc + OFT + (half*16 + 2*i + 1)*SPX + w*2);
            u[i] = lo | (hi << 16);
        }
        __nv_bfloat16* op = (half ? g_k : g_q) + (size_t)(b*WW + w0 + w)*DD;
        *(uint4*)op       = make_uint4(u[0], u[1], u[2], u[3]);
        *(uint4*)(op + 8) = make_uint4(u[4], u[5], u[6], u[7]);
    }
}

// ===========================================================================
// Kernel 2: row sums l_j = sum_w exp2(S[j,w]) (f16x2 packed exp), then
// scale g_v columns [j0, j0+128) in place by 1/l  (folds softmax norm into V;
// each CTA owns a disjoint column range -> race-free).
// ===========================================================================
#define SKD 48
__global__ void __launch_bounds__(256, 2) k_stats()
{
    __shared__ __align__(16) char smc[3*128*SKD];
    __shared__ float red[128];
    __shared__ uint32_t lpk[64];     // bf16x2-packed 1/l pairs
    const uint32_t smb = smem_u32(smc);
    const int tid = threadIdx.x;
    const int wid = tid >> 5;
    const int lane = tid & 31;
    const int g = lane >> 2, t = lane & 3;
    const int b = blockIdx.y, j0 = blockIdx.x * 128;
    const uint32_t QS = smb, KS = smb + 128*SKD;

    {
        int r = tid >> 1, h = tid & 1;
        CP16(QS + r*SKD + h*16, (const char*)(g_q + (size_t)(b*WW + j0 + r)*DD) + h*16);
    }
    {
        int r = tid >> 1, h = tid & 1;
        CP16(KS + r*SKD + h*16, (const char*)(g_k + (size_t)(b*WW + r)*DD) + h*16);
    }
    CP_COMMIT(); CP_WAIT0();
    __syncthreads();

    uint32_t a[4];
    {
        const char* r0 = smc + (wid*16 + g)*SKD + t*4;
        const char* r1 = smc + (wid*16 + g + 8)*SKD + t*4;
        a[0] = *(const uint32_t*)r0;
        a[1] = *(const uint32_t*)r1;
        a[2] = *(const uint32_t*)(r0 + 16);
        a[3] = *(const uint32_t*)(r1 + 16);
    }

    float l0 = 0.0f, l1 = 0.0f;
    for (int wt = 0; wt < 32; wt++) {
        const char* kb = smc + 128*SKD + (wt & 1)*(128*SKD);
        if (wt + 1 < 32) {
            int r = tid >> 1, h = tid & 1;
            CP16(KS + ((wt + 1) & 1)*(128*SKD) + r*SKD + h*16,
                 (const char*)(g_k + (size_t)(b*WW + (wt + 1)*128 + r)*DD) + h*16);
        }
        CP_COMMIT();
        uint32_t acc01 = 0, acc23 = 0;     // f16x2 pair accumulators (16 terms)
        #pragma unroll
        for (int nt = 0; nt < 16; nt++) {
            const char* baddr = kb + (nt*8 + g)*SKD + t*4;
            uint32_t b0 = *(const uint32_t*)baddr;
            uint32_t b1 = *(const uint32_t*)(baddr + 16);
            float d[4];
            mma_z(d, a, b0, b1);
            uint32_t h01, h23;
            asm("cvt.rn.f16x2.f32 %0, %1, %2;" : "=r"(h01) : "f"(d[1]), "f"(d[0]));
            asm("cvt.rn.f16x2.f32 %0, %1, %2;" : "=r"(h23) : "f"(d[3]), "f"(d[2]));
            asm("ex2.approx.f16x2 %0, %0;" : "+r"(h01));
            asm("ex2.approx.f16x2 %0, %0;" : "+r"(h23));
            asm("add.rn.f16x2 %0, %0, %1;" : "+r"(acc01) : "r"(h01));
            asm("add.rn.f16x2 %0, %0, %1;" : "+r"(acc23) : "r"(h23));
        }
        {   // flush pair accumulators to f32
            float f0, f1, f2, f3;
            asm("{.reg .f16 lo, hi; mov.b32 {lo, hi}, %2; cvt.f32.f16 %0, lo; cvt.f32.f16 %1, hi;}"
                : "=f"(f0), "=f"(f1) : "r"(acc01));
            asm("{.reg .f16 lo, hi; mov.b32 {lo, hi}, %2; cvt.f32.f16 %0, lo; cvt.f32.f16 %1, hi;}"
                : "=f"(f2), "=f"(f3) : "r"(acc23));
            l0 += f0 + f1;
            l1 += f2 + f3;
        }
        CP_WAIT0();
        __syncthreads();
    }
    #pragma unroll
    for (int off = 1; off < 4; off <<= 1) {
        l0 += __shfl_down_sync(0xffffffffu, l0, off, 4);
        l1 += __shfl_down_sync(0xffffffffu, l1, off, 4);
    }
    if (t == 0) {
        red[wid*16 + g]     = 1.0f / l0;
        red[wid*16 + g + 8] = 1.0f / l1;
    }
    __syncthreads();
    if (tid < 64)
        lpk[tid] = bf2u(__floats2bfloat162_rn(red[2*tid], red[2*tid + 1]));
    __syncthreads();

    // ---- scale g_v[:, j0:j0+128] by 1/l (in place, bf16x2 muls) ----
    {
        const int chunk = tid & 15;            // 8-wide j sub-chunk
        const int cb    = tid >> 4;            // c stride 16
        uint32_t s0 = lpk[chunk*4], s1 = lpk[chunk*4 + 1];
        uint32_t s2 = lpk[chunk*4 + 2], s3 = lpk[chunk*4 + 3];
        #pragma unroll
        for (int c = cb; c < 128; c += 16) {
            uint32_t* vp = (uint32_t*)(g_v + (size_t)(b*CC + c)*WW + j0 + chunk*8);
            uint4 v = *(uint4*)vp;
            asm("mul.rn.bf16x2 %0, %0, %1;" : "+r"(v.x) : "r"(s0));
            asm("mul.rn.bf16x2 %0, %0, %1;" : "+r"(v.y) : "r"(s1));
            asm("mul.rn.bf16x2 %0, %0, %1;" : "+r"(v.z) : "r"(s2));
            asm("mul.rn.bf16x2 %0, %0, %1;" : "+r"(v.w) : "r"(s3));
            *(uint4*)vp = v;
        }
    }
}

// ===========================================================================
// Kernel 3: context + residual, software-pipelined; epilogue is pure
// bf16x2 exp2 (v already carries 1/l). One sync per iteration.
// smem: ks@0 (6144), qring@6144 (4x3072), vs@18432 (2x18432),
//       Pt@55296 (2x18432). total 92160.
// ===========================================================================
#define SPJ 144
#define OF_KS 0
#define OF_QR 6144
#define OF_VS 18432
#define OF_PT 55296

__global__ void __launch_bounds__(256, 2) k_ctx(const float* __restrict__ x,
                                                float* __restrict__ out)
{
    extern __shared__ __align__(16) char smc[];
    const uint32_t smb = smem_u32(smc);
    const int tid = threadIdx.x;
    const int wid = tid >> 5;
    const int lane = tid & 31;
    const int g = lane >> 2, t = lane & 3;
    const int b = blockIdx.y, w0 = blockIdx.x * 128;

    {
        int r = tid >> 1, h = tid & 1;
        CP16(smb + OF_KS + r*SKD + h*16,
             (const char*)(g_k + (size_t)(b*WW + w0 + r)*DD) + h*16);
    }
    {
        int r = tid >> 2, h = tid & 3;
        CP8(smb + OF_QR + r*SKD + h*8,
            (const char*)(g_q + (size_t)(b*WW + r)*DD) + h*8);
    }
    CP_COMMIT(); CP_WAIT0();
    __syncthreads();

    uint32_t ak[4];
    {
        const char* r0 = smc + OF_KS + (wid*16 + g)*SKD + t*4;
        const char* r1 = smc + OF_KS + (wid*16 + g + 8)*SKD + t*4;
        ak[0] = *(const uint32_t*)r0;
        ak[1] = *(const uint32_t*)r1;
        ak[2] = *(const uint32_t*)(r0 + 16);
        ak[3] = *(const uint32_t*)(r1 + 16);
    }

    const int c0w = (wid & 3) * 32;
    const int wc0 = (wid >> 2) * 64;
    float acc[2][8][4];
    #pragma unroll
    for (int mt = 0; mt < 2; mt++)
        #pragma unroll
        for (int nt = 0; nt < 8; nt++)
            #pragma unroll
            for (int e = 0; e < 4; e++) acc[mt][nt][e] = 0.0f;

    for (int jt = -1; jt < 64; jt++) {
        if (jt + 2 < 64) {
            int r = tid >> 2, h = tid & 3;
            CP8(smb + OF_QR + ((jt + 2) & 3)*3072 + r*SKD + h*8,
                (const char*)(g_q + (size_t)(b*WW + (jt + 2)*64 + r)*DD) + h*8);
        }
        if (jt + 1 < 64) {
            #pragma unroll
            for (int i = 0; i < 4; i++) {
                int cid = tid + i*256;
                int c = cid >> 3, ch = cid & 7;
                CP16(smb + OF_VS + ((jt + 1) & 1)*18432 + c*SPJ + ch*16,
                     (const char*)(g_v + (size_t)(b*CC + c)*WW + (jt + 1)*64) + ch*16);
            }
        }
        CP_COMMIT();

        // ---- QK(jt+1) -> Pt[(jt+1)&1]: pure bf16x2 exp2 epilogue ----
        if (jt + 1 < 64) {
            const char* qb = smc + OF_QR + ((jt + 1) & 3)*3072;
            char* ptb = smc + OF_PT + ((jt + 1) & 1)*18432;
            #pragma unroll
            for (int nt = 0; nt < 8; nt++) {
                const char* baddr = qb + (nt*8 + g)*SKD + t*4;
                uint32_t b0 = *(const uint32_t*)baddr;
                uint32_t b1 = *(const uint32_t*)(baddr + 16);
                float d[4];
                mma_z(d, ak, b0, b1);
                uint32_t u0, u1;
                asm("cvt.rn.bf16x2.f32 %0, %1, %2;" : "=r"(u0) : "f"(d[1]), "f"(d[0]));
                asm("cvt.rn.bf16x2.f32 %0, %1, %2;" : "=r"(u1) : "f"(d[3]), "f"(d[2]));
                asm("ex2.approx.ftz.bf16x2 %0, %0;" : "+r"(u0));
                asm("ex2.approx.ftz.bf16x2 %0, %0;" : "+r"(u1));
                *(uint32_t*)(ptb + (wid*16 + g)*SPJ     + (nt*8 + 2*t)*2) = u0;
                *(uint32_t*)(ptb + (wid*16 + g + 8)*SPJ + (nt*8 + 2*t)*2) = u1;
            }
        }

        // ---- PV(jt) <- Pt[jt&1], vs[jt&1] ----
        if (jt >= 0) {
            const char* vb = smc + OF_VS + (jt & 1)*18432;
            const char* pt = smc + OF_PT + (jt & 1)*18432;
            #pragma unroll
            for (int k0 = 0; k0 < 4; k0++) {
                uint32_t av[2][4];
                #pragma unroll
                for (int mt = 0; mt < 2; mt++) {
                    const char* r0 = vb + (c0w + mt*16 + g)*SPJ + k0*32 + t*4;
                    const char* r1 = r0 + 8*SPJ;
                    av[mt][0] = *(const uint32_t*)r0;
                    av[mt][1] = *(const uint32_t*)r1;
                    av[mt][2] = *(const uint32_t*)(r0 + 16);
                    av[mt][3] = *(const uint32_t*)(r1 + 16);
                }
                #pragma unroll
                for (int nt = 0; nt < 8; nt++) {
                    const char* pb = pt + (wc0 + nt*8 + g)*SPJ + k0*32 + t*4;
                    uint32_t b0 = *(const uint32_t*)pb;
                    uint32_t b1 = *(const uint32_t*)(pb + 16);
                    mma_acc(acc[0][nt], av[0], b0, b1);
                    mma_acc(acc[1][nt], av[1], b0, b1);
                }
            }
        }

        CP_WAIT0();
        __syncthreads();
    }

    // ---- epilogue: out = acc + x ----
    #pragma unroll
    for (int mt = 0; mt < 2; mt++) {
        #pragma unroll
        for (int nt = 0; nt < 8; nt++) {
            int c  = c0w + mt*16 + g;
            int wc = w0 + wc0 + nt*8 + 2*t;
            size_t i0 = (size_t)(b*CC + c)*WW + wc;
            size_t i1 = i0 + 8*WW;
            float2 x0 = *(const float2*)(x + i0);
            float2 x1 = *(const float2*)(x + i1);
            *(float2*)(out + i0) = make_float2(acc[mt][nt][0] + x0.x,
                                               acc[mt][nt][1] + x0.y);
            *(float2*)(out + i1) = make_float2(acc[mt][nt][2] + x1.x,
                                               acc[mt][nt][3] + x1.y);
        }
    }
}

// ===========================================================================
extern "C" void kernel_launch(void* const* d_in, const int* in_sizes, int n_in,
                              void* d_out, int out_size)
{
    const float* x  = (const float*)d_in[0];
    const float* Wq = (const float*)d_in[1];
    const float* bq = (const float*)d_in[2];
    const float* Wk = (const float*)d_in[3];
    const float* bk = (const float*)d_in[4];
    const float* Wv = (const float*)d_in[5];
    const float* bv = (const float*)d_in[6];
    float* out = (float*)d_out;

    const int smem_proj = 87040;
    const int smem_ctx  = 92160;
    cudaFuncSetAttribute(k_proj, cudaFuncAttributeMaxDynamicSharedMemorySize, smem_proj);
    cudaFuncSetAttribute(k_ctx,  cudaFuncAttributeMaxDynamicSharedMemorySize, smem_ctx);

    dim3 g(WW/128, BB);
    k_proj <<<g, 256, smem_proj>>>(x, Wq, bq, Wk, bk, Wv, bv);
    k_stats<<<g, 256>>>();
    k_ctx  <<<g, 256, smem_ctx>>>(x, out);
}

// round 9
// speedup vs baseline: 19.8081x; 1.1739x over previous
#include <cuda_runtime.h>
#include <cuda_bf16.h>
#include <cstdint>

#define BB 8
#define CC 128
#define WW 4096
#define DD 16

// 0.25 (= D^-0.5) * log2(e): folded into q so softmax uses exp2 directly.
#define QSCALE 0.3606737602222409f

typedef unsigned long long ull;

// ---- scratch (__device__ globals; no allocs allowed) ----------------------
__device__ __nv_bfloat16 g_q[(size_t)BB*WW*DD];   // [b][w][d], pre-scaled
__device__ __nv_bfloat16 g_k[(size_t)BB*WW*DD];   // [b][w][d]
__device__ __nv_bfloat16 g_v[(size_t)BB*CC*WW];   // [b][c][w]; later scaled by linv[j]

// ---- helpers --------------------------------------------------------------
__device__ __forceinline__ uint32_t smem_u32(const void* p) {
    uint32_t a;
    asm("{ .reg .u64 t; cvta.to.shared.u64 t, %1; cvt.u32.u64 %0, t; }"
        : "=r"(a) : "l"(p));
    return a;
}
__device__ __forceinline__ uint32_t bf2u(__nv_bfloat162 h) {
    return *reinterpret_cast<uint32_t*>(&h);
}

// ---- mma.sync m16n8k16 bf16 (A row-major, B col-major, f32 accum) ---------
__device__ __forceinline__ void mma_acc(float* d, const uint32_t* a,
                                        uint32_t b0, uint32_t b1) {
    asm volatile("mma.sync.aligned.m16n8k16.row.col.f32.bf16.bf16.f32 "
        "{%0,%1,%2,%3}, {%4,%5,%6,%7}, {%8,%9}, {%0,%1,%2,%3};"
        : "+f"(d[0]), "+f"(d[1]), "+f"(d[2]), "+f"(d[3])
        : "r"(a[0]), "r"(a[1]), "r"(a[2]), "r"(a[3]), "r"(b0), "r"(b1));
}
__device__ __forceinline__ void mma_z(float* d, const uint32_t* a,
                                      uint32_t b0, uint32_t b1) {
    asm volatile("mma.sync.aligned.m16n8k16.row.col.f32.bf16.bf16.f32 "
        "{%0,%1,%2,%3}, {%4,%5,%6,%7}, {%8,%9}, {%10,%10,%10,%10};"
        : "=f"(d[0]), "=f"(d[1]), "=f"(d[2]), "=f"(d[3])
        : "r"(a[0]), "r"(a[1]), "r"(a[2]), "r"(a[3]), "r"(b0), "r"(b1),
          "f"(0.0f));
}

// ---- cp.async -------------------------------------------------------------
#define CP16(dst, src) asm volatile("cp.async.cg.shared.global [%0], [%1], 16;" :: "r"(dst), "l"(src))
#define CP8(dst, src)  asm volatile("cp.async.ca.shared.global [%0], [%1], 8;"  :: "r"(dst), "l"(src))
#define CP_COMMIT()    asm volatile("cp.async.commit_group;" ::: "memory")
#define CP_WAIT0()     asm volatile("cp.async.wait_group 0;" ::: "memory")

// ===========================================================================
// Kernel 1: projections via bf16 HMMA (unchanged from R6).
// ===========================================================================
#define SPX 272
#define OFX 0
#define OFW 34816
#define OFQ 69632
#define OFT 78336

__global__ void __launch_bounds__(256) k_proj(
    const float* __restrict__ x,
    const float* __restrict__ Wq, const float* __restrict__ bq,
    const float* __restrict__ Wk, const float* __restrict__ bk,
    const float* __restrict__ Wv, const float* __restrict__ bv)
{
    extern __shared__ __align__(16) char smc[];
    const int b   = blockIdx.y;
    const int w0  = blockIdx.x * 128;
    const int tid = threadIdx.x;
    const int wid = tid >> 5;
    const int lane = tid & 31;
    const int g = lane >> 2, t = lane & 3;

    for (int i = tid; i < 128*32; i += 256) {
        int r = i >> 5, cf = i & 31;
        float4 v = *(const float4*)(Wv + r*128 + cf*4);
        uint2 o;
        o.x = bf2u(__floats2bfloat162_rn(v.x, v.y));
        o.y = bf2u(__floats2bfloat162_rn(v.z, v.w));
        *(uint2*)(smc + OFW + r*SPX + cf*8) = o;
    }
    for (int i = tid; i < 32*32; i += 256) {
        int r = i >> 5, cf = i & 31;
        const float* src = (r < 16) ? (Wq + r*128 + cf*4) : (Wk + (r-16)*128 + cf*4);
        float4 v = *(const float4*)src;
        uint2 o;
        o.x = bf2u(__floats2bfloat162_rn(v.x, v.y));
        o.y = bf2u(__floats2bfloat162_rn(v.z, v.w));
        *(uint2*)(smc + OFQ + r*SPX + cf*8) = o;
    }
    {
        const int c = tid & 127, hf = tid >> 7;
        const float* xp = x + (size_t)(b*CC + c)*WW + w0 + hf*64;
        #pragma unroll
        for (int it = 0; it < 16; it++) {
            float4 v = *(const float4*)(xp + it*4);
            int w = hf*64 + it*4;
            *(__nv_bfloat16*)(smc + OFX + (w  )*SPX + c*2) = __float2bfloat16(v.x);
            *(__nv_bfloat16*)(smc + OFX + (w+1)*SPX + c*2) = __float2bfloat16(v.y);
            *(__nv_bfloat16*)(smc + OFX + (w+2)*SPX + c*2) = __float2bfloat16(v.z);
            *(__nv_bfloat16*)(smc + OFX + (w+3)*SPX + c*2) = __float2bfloat16(v.w);
        }
    }
    __syncthreads();

    {   // V GEMM
        const int mb = wid * 16;
        uint32_t A[8][4];
        #pragma unroll
        for (int kt = 0; kt < 8; kt++) {
            const char* r0 = smc + OFW + (mb + g)*SPX + kt*32 + t*4;
            const char* r1 = smc + OFW + (mb + g + 8)*SPX + kt*32 + t*4;
            A[kt][0] = *(const uint32_t*)r0;
            A[kt][1] = *(const uint32_t*)r1;
            A[kt][2] = *(const uint32_t*)(r0 + 16);
            A[kt][3] = *(const uint32_t*)(r1 + 16);
        }
        const float bias0 = bv[mb + g], bias1 = bv[mb + g + 8];
        #pragma unroll
        for (int nt = 0; nt < 16; nt++) {
            float acc[4] = {bias0, bias0, bias1, bias1};
            #pragma unroll
            for (int kt = 0; kt < 8; kt++) {
                const char* bp = smc + OFX + (nt*8 + g)*SPX + kt*32 + t*4;
                uint32_t b0 = *(const uint32_t*)bp;
                uint32_t b1 = *(const uint32_t*)(bp + 16);
                mma_acc(acc, A[kt], b0, b1);
            }
            const int wcol = w0 + nt*8 + 2*t;
            *(uint32_t*)(g_v + (size_t)(b*CC + mb + g)*WW + wcol) =
                bf2u(__floats2bfloat162_rn(acc[0], acc[1]));
            *(uint32_t*)(g_v + (size_t)(b*CC + mb + g + 8)*WW + wcol) =
                bf2u(__floats2bfloat162_rn(acc[2], acc[3]));
        }
    }

    {   // QK GEMM
        const int mt = wid & 1, ntb = (wid >> 1) * 4;
        uint32_t A[8][4];
        #pragma unroll
        for (int kt = 0; kt < 8; kt++) {
            const char* r0 = smc + OFQ + (mt*16 + g)*SPX + kt*32 + t*4;
            const char* r1 = smc + OFQ + (mt*16 + g + 8)*SPX + kt*32 + t*4;
            A[kt][0] = *(const uint32_t*)r0;
            A[kt][1] = *(const uint32_t*)r1;
            A[kt][2] = *(const uint32_t*)(r0 + 16);
            A[kt][3] = *(const uint32_t*)(r1 + 16);
        }
        const float* bias = mt ? bk : bq;
        const float bias0 = bias[g], bias1 = bias[g + 8];
        const float psc = mt ? 1.0f : QSCALE;
        #pragma unroll
        for (int nt = ntb; nt < ntb + 4; nt++) {
            float acc[4] = {bias0, bias0, bias1, bias1};
            #pragma unroll
            for (int kt = 0; kt < 8; kt++) {
                const char* bp = smc + OFX + (nt*8 + g)*SPX + kt*32 + t*4;
                uint32_t b0 = *(const uint32_t*)bp;
                uint32_t b1 = *(const uint32_t*)(bp + 16);
                mma_acc(acc, A[kt], b0, b1);
            }
            const int wcol = nt*8 + 2*t;
            *(uint32_t*)(smc + OFT + (mt*16 + g)*SPX + wcol*2) =
                bf2u(__floats2bfloat162_rn(acc[0]*psc, acc[1]*psc));
            *(uint32_t*)(smc + OFT + (mt*16 + g + 8)*SPX + wcol*2) =
                bf2u(__floats2bfloat162_rn(acc[2]*psc, acc[3]*psc));
        }
    }
    __syncthreads();

    {   // transpose qkT -> g_q/g_k [w][16]
        const int w = tid & 127, half = tid >> 7;
        uint32_t u[8];
        #pragma unroll
        for (int i = 0; i < 8; i++) {
            uint32_t lo = *(const uint16_t*)(smc + OFT + (half*16 + 2*i    )*SPX + w*2);
            uint32_t hi = *(const uint16_t*)(smc + OFT + (half*16 + 2*i + 1)*SPX + w*2);
            u[i] = lo | (hi << 16);
        }
        __nv_bfloat16* op = (half ? g_k : g_q) + (size_t)(b*WW + w0 + w)*DD;
        *(uint4*)op       = make_uint4(u[0], u[1], u[2], u[3]);
        *(uint4*)(op + 8) = make_uint4(u[4], u[5], u[6], u[7]);
    }
}

// ===========================================================================
// Kernel 2: row sums + fold 1/l into V (unchanged from R8).
// ===========================================================================
#define SKD 48
__global__ void __launch_bounds__(256, 2) k_stats()
{
    __shared__ __align__(16) char smc[3*128*SKD];
    __shared__ float red[128];
    __shared__ uint32_t lpk[64];
    const uint32_t smb = smem_u32(smc);
    const int tid = threadIdx.x;
    const int wid = tid >> 5;
    const int lane = tid & 31;
    const int g = lane >> 2, t = lane & 3;
    const int b = blockIdx.y, j0 = blockIdx.x * 128;
    const uint32_t QS = smb, KS = smb + 128*SKD;

    {
        int r = tid >> 1, h = tid & 1;
        CP16(QS + r*SKD + h*16, (const char*)(g_q + (size_t)(b*WW + j0 + r)*DD) + h*16);
    }
    {
        int r = tid >> 1, h = tid & 1;
        CP16(KS + r*SKD + h*16, (const char*)(g_k + (size_t)(b*WW + r)*DD) + h*16);
    }
    CP_COMMIT(); CP_WAIT0();
    __syncthreads();

    uint32_t a[4];
    {
        const char* r0 = smc + (wid*16 + g)*SKD + t*4;
        const char* r1 = smc + (wid*16 + g + 8)*SKD + t*4;
        a[0] = *(const uint32_t*)r0;
        a[1] = *(const uint32_t*)r1;
        a[2] = *(const uint32_t*)(r0 + 16);
        a[3] = *(const uint32_t*)(r1 + 16);
    }

    float l0 = 0.0f, l1 = 0.0f;
    for (int wt = 0; wt < 32; wt++) {
        const char* kb = smc + 128*SKD + (wt & 1)*(128*SKD);
        if (wt + 1 < 32) {
            int r = tid >> 1, h = tid & 1;
            CP16(KS + ((wt + 1) & 1)*(128*SKD) + r*SKD + h*16,
                 (const char*)(g_k + (size_t)(b*WW + (wt + 1)*128 + r)*DD) + h*16);
        }
        CP_COMMIT();
        uint32_t acc01 = 0, acc23 = 0;
        #pragma unroll
        for (int nt = 0; nt < 16; nt++) {
            const char* baddr = kb + (nt*8 + g)*SKD + t*4;
            uint32_t b0 = *(const uint32_t*)baddr;
            uint32_t b1 = *(const uint32_t*)(baddr + 16);
            float d[4];
            mma_z(d, a, b0, b1);
            uint32_t h01, h23;
            asm("cvt.rn.f16x2.f32 %0, %1, %2;" : "=r"(h01) : "f"(d[1]), "f"(d[0]));
            asm("cvt.rn.f16x2.f32 %0, %1, %2;" : "=r"(h23) : "f"(d[3]), "f"(d[2]));
            asm("ex2.approx.f16x2 %0, %0;" : "+r"(h01));
            asm("ex2.approx.f16x2 %0, %0;" : "+r"(h23));
            asm("add.rn.f16x2 %0, %0, %1;" : "+r"(acc01) : "r"(h01));
            asm("add.rn.f16x2 %0, %0, %1;" : "+r"(acc23) : "r"(h23));
        }
        {
            float f0, f1, f2, f3;
            asm("{.reg .f16 lo, hi; mov.b32 {lo, hi}, %2; cvt.f32.f16 %0, lo; cvt.f32.f16 %1, hi;}"
                : "=f"(f0), "=f"(f1) : "r"(acc01));
            asm("{.reg .f16 lo, hi; mov.b32 {lo, hi}, %2; cvt.f32.f16 %0, lo; cvt.f32.f16 %1, hi;}"
                : "=f"(f2), "=f"(f3) : "r"(acc23));
            l0 += f0 + f1;
            l1 += f2 + f3;
        }
        CP_WAIT0();
        __syncthreads();
    }
    #pragma unroll
    for (int off = 1; off < 4; off <<= 1) {
        l0 += __shfl_down_sync(0xffffffffu, l0, off, 4);
        l1 += __shfl_down_sync(0xffffffffu, l1, off, 4);
    }
    if (t == 0) {
        red[wid*16 + g]     = 1.0f / l0;
        red[wid*16 + g + 8] = 1.0f / l1;
    }
    __syncthreads();
    if (tid < 64)
        lpk[tid] = bf2u(__floats2bfloat162_rn(red[2*tid], red[2*tid + 1]));
    __syncthreads();

    {
        const int chunk = tid & 15;
        const int cb    = tid >> 4;
        uint32_t s0 = lpk[chunk*4], s1 = lpk[chunk*4 + 1];
        uint32_t s2 = lpk[chunk*4 + 2], s3 = lpk[chunk*4 + 3];
        #pragma unroll
        for (int c = cb; c < 128; c += 16) {
            uint32_t* vp = (uint32_t*)(g_v + (size_t)(b*CC + c)*WW + j0 + chunk*8);
            uint4 v = *(uint4*)vp;
            asm("mul.rn.bf16x2 %0, %0, %1;" : "+r"(v.x) : "r"(s0));
            asm("mul.rn.bf16x2 %0, %0, %1;" : "+r"(v.y) : "r"(s1));
            asm("mul.rn.bf16x2 %0, %0, %1;" : "+r"(v.z) : "r"(s2));
            asm("mul.rn.bf16x2 %0, %0, %1;" : "+r"(v.w) : "r"(s3));
            *(uint4*)vp = v;
        }
    }
}

// ===========================================================================
// Kernel 3: context + residual. P NEVER TOUCHES SMEM: QK C-frags (exp2'd,
// bf16x2-packed) are directly the PV A-frags (out[w][c] = P x v^T, B=v via
// ldmatrix.x4). One __syncthreads per iteration (v buffer rotation only).
// smem: ks@0 (6144), qring@6144 (4x3072), vs@18432 (2x18432) = 55296 B.
// ===========================================================================
#define SPJ 144
#define OF_KS 0
#define OF_QR 6144
#define OF_VS 18432

__global__ void __launch_bounds__(256, 2) k_ctx(const float* __restrict__ x,
                                                float* __restrict__ out)
{
    extern __shared__ __align__(16) char smc[];
    const uint32_t smb = smem_u32(smc);
    const int tid = threadIdx.x;
    const int wid = tid >> 5;
    const int lane = tid & 31;
    const int g = lane >> 2, t = lane & 3;
    const int b = blockIdx.y, w0 = blockIdx.x * 128;

    // ---- preamble: ks (fixed), q tiles 0,1, v tile 0 ----
    {
        int r = tid >> 1, h = tid & 1;
        CP16(smb + OF_KS + r*SKD + h*16,
             (const char*)(g_k + (size_t)(b*WW + w0 + r)*DD) + h*16);
    }
    {
        int r = tid >> 2, h = tid & 3;
        CP8(smb + OF_QR + r*SKD + h*8,
            (const char*)(g_q + (size_t)(b*WW + r)*DD) + h*8);
        CP8(smb + OF_QR + 3072 + r*SKD + h*8,
            (const char*)(g_q + (size_t)(b*WW + 64 + r)*DD) + h*8);
    }
    #pragma unroll
    for (int i = 0; i < 4; i++) {
        int cid = tid + i*256;
        int c = cid >> 3, ch = cid & 7;
        CP16(smb + OF_VS + c*SPJ + ch*16,
             (const char*)(g_v + (size_t)(b*CC + c)*WW) + ch*16);
    }
    CP_COMMIT(); CP_WAIT0();
    __syncthreads();

    // A fragments for QK (k rows = warp's 16 w rows), fixed
    uint32_t ak[4];
    {
        const char* r0 = smc + OF_KS + (wid*16 + g)*SKD + t*4;
        const char* r1 = smc + OF_KS + (wid*16 + g + 8)*SKD + t*4;
        ak[0] = *(const uint32_t*)r0;
        ak[1] = *(const uint32_t*)r1;
        ak[2] = *(const uint32_t*)(r0 + 16);
        ak[3] = *(const uint32_t*)(r1 + 16);
    }

    // ldmatrix per-lane address offset within a v buffer:
    // matrix id mi = lane>>3:  mi>>1 selects ct parity, mi&1 selects b0/b1.
    const uint32_t vlane = (uint32_t)((((lane >> 4)*8 + (lane & 7))*SPJ)
                                      + ((lane >> 3) & 1)*16);

    float acc[16][4];
    #pragma unroll
    for (int ct = 0; ct < 16; ct++)
        #pragma unroll
        for (int e = 0; e < 4; e++) acc[ct][e] = 0.0f;

    for (int jt = 0; jt < 64; jt++) {
        // ---- prefetch q(jt+2), v(jt+1) ----
        if (jt + 2 < 64) {
            int r = tid >> 2, h = tid & 3;
            CP8(smb + OF_QR + ((jt + 2) & 3)*3072 + r*SKD + h*8,
                (const char*)(g_q + (size_t)(b*WW + (jt + 2)*64 + r)*DD) + h*8);
        }
        if (jt + 1 < 64) {
            #pragma unroll
            for (int i = 0; i < 4; i++) {
                int cid = tid + i*256;
                int c = cid >> 3, ch = cid & 7;
                CP16(smb + OF_VS + ((jt + 1) & 1)*18432 + c*SPJ + ch*16,
                     (const char*)(g_v + (size_t)(b*CC + c)*WW + (jt + 1)*64) + ch*16);
            }
        }
        CP_COMMIT();

        const char* qb = smc + OF_QR + (jt & 3)*3072;
        const uint32_t vb = smb + OF_VS + (jt & 1)*18432 + vlane;

        #pragma unroll
        for (int ks = 0; ks < 4; ks++) {
            // ---- QK for nt = 2ks, 2ks+1 -> P A-fragments (registers) ----
            uint32_t A[4];
            {
                const char* p0 = qb + ((2*ks)*8 + g)*SKD + t*4;
                float d[4];
                mma_z(d, ak, *(const uint32_t*)p0, *(const uint32_t*)(p0 + 16));
                asm("cvt.rn.bf16x2.f32 %0, %1, %2;" : "=r"(A[0]) : "f"(d[1]), "f"(d[0]));
                asm("cvt.rn.bf16x2.f32 %0, %1, %2;" : "=r"(A[1]) : "f"(d[3]), "f"(d[2]));
                const char* p1 = qb + ((2*ks + 1)*8 + g)*SKD + t*4;
                mma_z(d, ak, *(const uint32_t*)p1, *(const uint32_t*)(p1 + 16));
                asm("cvt.rn.bf16x2.f32 %0, %1, %2;" : "=r"(A[2]) : "f"(d[1]), "f"(d[0]));
                asm("cvt.rn.bf16x2.f32 %0, %1, %2;" : "=r"(A[3]) : "f"(d[3]), "f"(d[2]));
                asm("ex2.approx.ftz.bf16x2 %0, %0;" : "+r"(A[0]));
                asm("ex2.approx.ftz.bf16x2 %0, %0;" : "+r"(A[1]));
                asm("ex2.approx.ftz.bf16x2 %0, %0;" : "+r"(A[2]));
                asm("ex2.approx.ftz.bf16x2 %0, %0;" : "+r"(A[3]));
            }
            // ---- PV: out[w][c] += P x v^T, B frags via ldmatrix.x4 ----
            #pragma unroll
            for (int cp = 0; cp < 8; cp++) {
                uint32_t v0, v1, v2, v3;
                uint32_t ad = vb + (uint32_t)(cp*(16*SPJ) + ks*32);
                asm volatile("ldmatrix.sync.aligned.m8n8.x4.shared.b16 "
                    "{%0,%1,%2,%3}, [%4];"
                    : "=r"(v0), "=r"(v1), "=r"(v2), "=r"(v3) : "r"(ad));
                mma_acc(acc[2*cp],     A, v0, v1);
                mma_acc(acc[2*cp + 1], A, v2, v3);
            }
        }
        CP_WAIT0();
        __syncthreads();
    }

    // ---- epilogue: out = acc + x.  thread: w rows g/g+8, c = ct*8+2t(+1) ----
    const int wbase = w0 + wid*16;
    #pragma unroll
    for (int ct = 0; ct < 16; ct++) {
        size_t base = (size_t)(b*CC + ct*8 + 2*t)*WW + wbase;
        out[base + g]          = acc[ct][0] + x[base + g];
        out[base + g + 8]      = acc[ct][2] + x[base + g + 8];
        out[base + WW + g]     = acc[ct][1] + x[base + WW + g];
        out[base + WW + g + 8] = acc[ct][3] + x[base + WW + g + 8];
    }
}

// ===========================================================================
extern "C" void kernel_launch(void* const* d_in, const int* in_sizes, int n_in,
                              void* d_out, int out_size)
{
    const float* x  = (const float*)d_in[0];
    const float* Wq = (const float*)d_in[1];
    const float* bq = (const float*)d_in[2];
    const float* Wk = (const float*)d_in[3];
    const float* bk = (const float*)d_in[4];
    const float* Wv = (const float*)d_in[5];
    const float* bv = (const float*)d_in[6];
    float* out = (float*)d_out;

    const int smem_proj = 87040;
    const int smem_ctx  = 55296;
    cudaFuncSetAttribute(k_proj, cudaFuncAttributeMaxDynamicSharedMemorySize, smem_proj);
    cudaFuncSetAttribute(k_ctx,  cudaFuncAttributeMaxDynamicSharedMemorySize, smem_ctx);

    dim3 g(WW/128, BB);
    k_proj <<<g, 256, smem_proj>>>(x, Wq, bq, Wk, bk, Wv, bv);
    k_stats<<<g, 256>>>();
    k_ctx  <<<g, 256, smem_ctx>>>(x, out);
}

// round 10
// speedup vs baseline: 20.0843x; 1.0139x over previous
#include <cuda_runtime.h>
#include <cuda_bf16.h>
#include <cstdint>

#define BB 8
#define CC 128
#define WW 4096
#define DD 16

// 0.25 (= D^-0.5) * log2(e): folded into q so softmax uses exp2 directly.
#define QSCALE 0.3606737602222409f

typedef unsigned long long ull;

// ---- scratch (__device__ globals; no allocs allowed) ----------------------
__device__ __nv_bfloat16 g_q[(size_t)BB*WW*DD];   // [b][w][d], pre-scaled
__device__ __nv_bfloat16 g_k[(size_t)BB*WW*DD];   // [b][w][d]
__device__ __nv_bfloat16 g_v[(size_t)BB*CC*WW];   // [b][c][w]; later scaled by linv[j]

// ---- helpers --------------------------------------------------------------
__device__ __forceinline__ uint32_t smem_u32(const void* p) {
    uint32_t a;
    asm("{ .reg .u64 t; cvta.to.shared.u64 t, %1; cvt.u32.u64 %0, t; }"
        : "=r"(a) : "l"(p));
    return a;
}
__device__ __forceinline__ uint32_t bf2u(__nv_bfloat162 h) {
    return *reinterpret_cast<uint32_t*>(&h);
}

// ---- mma.sync m16n8k16 bf16 (A row-major, B col-major, f32 accum) ---------
__device__ __forceinline__ void mma_acc(float* d, const uint32_t* a,
                                        uint32_t b0, uint32_t b1) {
    asm volatile("mma.sync.aligned.m16n8k16.row.col.f32.bf16.bf16.f32 "
        "{%0,%1,%2,%3}, {%4,%5,%6,%7}, {%8,%9}, {%0,%1,%2,%3};"
        : "+f"(d[0]), "+f"(d[1]), "+f"(d[2]), "+f"(d[3])
        : "r"(a[0]), "r"(a[1]), "r"(a[2]), "r"(a[3]), "r"(b0), "r"(b1));
}
__device__ __forceinline__ void mma_z(float* d, const uint32_t* a,
                                      uint32_t b0, uint32_t b1) {
    asm volatile("mma.sync.aligned.m16n8k16.row.col.f32.bf16.bf16.f32 "
        "{%0,%1,%2,%3}, {%4,%5,%6,%7}, {%8,%9}, {%10,%10,%10,%10};"
        : "=f"(d[0]), "=f"(d[1]), "=f"(d[2]), "=f"(d[3])
        : "r"(a[0]), "r"(a[1]), "r"(a[2]), "r"(a[3]), "r"(b0), "r"(b1),
          "f"(0.0f));
}
#define LDMX4(v0, v1, v2, v3, addr) \
    asm volatile("ldmatrix.sync.aligned.m8n8.x4.shared.b16 {%0,%1,%2,%3}, [%4];" \
        : "=r"(v0), "=r"(v1), "=r"(v2), "=r"(v3) : "r"(addr))

// ---- cp.async -------------------------------------------------------------
#define CP16(dst, src) asm volatile("cp.async.cg.shared.global [%0], [%1], 16;" :: "r"(dst), "l"(src))
#define CP8(dst, src)  asm volatile("cp.async.ca.shared.global [%0], [%1], 8;"  :: "r"(dst), "l"(src))
#define CP_COMMIT()    asm volatile("cp.async.commit_group;" ::: "memory")
#define CP_WAIT0()     asm volatile("cp.async.wait_group 0;" ::: "memory")

// ===========================================================================
// Kernel 1: projections via bf16 HMMA. x transpose now uses paired 32-bit
// smem stores (conflict-free) instead of scattered 2-byte stores.
// ===========================================================================
#define SPX 272
#define OFX 0
#define OFW 34816
#define OFQ 69632
#define OFT 78336

__global__ void __launch_bounds__(256) k_proj(
    const float* __restrict__ x,
    const float* __restrict__ Wq, const float* __restrict__ bq,
    const float* __restrict__ Wk, const float* __restrict__ bk,
    const float* __restrict__ Wv, const float* __restrict__ bv)
{
    extern __shared__ __align__(16) char smc[];
    const int b   = blockIdx.y;
    const int w0  = blockIdx.x * 128;
    const int tid = threadIdx.x;
    const int wid = tid >> 5;
    const int lane = tid & 31;
    const int g = lane >> 2, t = lane & 3;

    for (int i = tid; i < 128*32; i += 256) {
        int r = i >> 5, cf = i & 31;
        float4 v = *(const float4*)(Wv + r*128 + cf*4);
        uint2 o;
        o.x = bf2u(__floats2bfloat162_rn(v.x, v.y));
        o.y = bf2u(__floats2bfloat162_rn(v.z, v.w));
        *(uint2*)(smc + OFW + r*SPX + cf*8) = o;
    }
    for (int i = tid; i < 32*32; i += 256) {
        int r = i >> 5, cf = i & 31;
        const float* src = (r < 16) ? (Wq + r*128 + cf*4) : (Wk + (r-16)*128 + cf*4);
        float4 v = *(const float4*)src;
        uint2 o;
        o.x = bf2u(__floats2bfloat162_rn(v.x, v.y));
        o.y = bf2u(__floats2bfloat162_rn(v.z, v.w));
        *(uint2*)(smc + OFQ + r*SPX + cf*8) = o;
    }
    // ---- x -> xT[w][c] bf16: thread owns c-pair (2*c2, 2*c2+1), packs
    //      bf16x2 pairs, 32-bit conflict-free stores. ----
    {
        const int c2 = tid & 63;         // c = 2*c2
        const int wg = tid >> 6;         // 0..3
        #pragma unroll
        for (int chunk = 0; chunk < 4; chunk++) {
            const int wb = chunk*32 + wg*8;
            const float* xp0 = x + (size_t)(b*CC + 2*c2)*WW + w0 + wb;
            const float* xp1 = xp0 + WW;
            float4 a0 = *(const float4*)xp0;
            float4 a1 = *(const float4*)(xp0 + 4);
            float4 c0 = *(const float4*)xp1;
            float4 c1 = *(const float4*)(xp1 + 4);
            char* base = smc + OFX + c2*4;
            *(uint32_t*)(base + (wb  )*SPX) = bf2u(__floats2bfloat162_rn(a0.x, c0.x));
            *(uint32_t*)(base + (wb+1)*SPX) = bf2u(__floats2bfloat162_rn(a0.y, c0.y));
            *(uint32_t*)(base + (wb+2)*SPX) = bf2u(__floats2bfloat162_rn(a0.z, c0.z));
            *(uint32_t*)(base + (wb+3)*SPX) = bf2u(__floats2bfloat162_rn(a0.w, c0.w));
            *(uint32_t*)(base + (wb+4)*SPX) = bf2u(__floats2bfloat162_rn(a1.x, c1.x));
            *(uint32_t*)(base + (wb+5)*SPX) = bf2u(__floats2bfloat162_rn(a1.y, c1.y));
            *(uint32_t*)(base + (wb+6)*SPX) = bf2u(__floats2bfloat162_rn(a1.z, c1.z));
            *(uint32_t*)(base + (wb+7)*SPX) = bf2u(__floats2bfloat162_rn(a1.w, c1.w));
        }
    }
    __syncthreads();

    {   // V GEMM
        const int mb = wid * 16;
        uint32_t A[8][4];
        #pragma unroll
        for (int kt = 0; kt < 8; kt++) {
            const char* r0 = smc + OFW + (mb + g)*SPX + kt*32 + t*4;
            const char* r1 = smc + OFW + (mb + g + 8)*SPX + kt*32 + t*4;
            A[kt][0] = *(const uint32_t*)r0;
            A[kt][1] = *(const uint32_t*)r1;
            A[kt][2] = *(const uint32_t*)(r0 + 16);
            A[kt][3] = *(const uint32_t*)(r1 + 16);
        }
        const float bias0 = bv[mb + g], bias1 = bv[mb + g + 8];
        #pragma unroll
        for (int nt = 0; nt < 16; nt++) {
            float acc[4] = {bias0, bias0, bias1, bias1};
            #pragma unroll
            for (int kt = 0; kt < 8; kt++) {
                const char* bp = smc + OFX + (nt*8 + g)*SPX + kt*32 + t*4;
                uint32_t b0 = *(const uint32_t*)bp;
                uint32_t b1 = *(const uint32_t*)(bp + 16);
                mma_acc(acc, A[kt], b0, b1);
            }
            const int wcol = w0 + nt*8 + 2*t;
            *(uint32_t*)(g_v + (size_t)(b*CC + mb + g)*WW + wcol) =
                bf2u(__floats2bfloat162_rn(acc[0], acc[1]));
            *(uint32_t*)(g_v + (size_t)(b*CC + mb + g + 8)*WW + wcol) =
                bf2u(__floats2bfloat162_rn(acc[2], acc[3]));
        }
    }

    {   // QK GEMM
        const int mt = wid & 1, ntb = (wid >> 1) * 4;
        uint32_t A[8][4];
        #pragma unroll
        for (int kt = 0; kt < 8; kt++) {
            const char* r0 = smc + OFQ + (mt*16 + g)*SPX + kt*32 + t*4;
            const char* r1 = smc + OFQ + (mt*16 + g + 8)*SPX + kt*32 + t*4;
            A[kt][0] = *(const uint32_t*)r0;
            A[kt][1] = *(const uint32_t*)r1;
            A[kt][2] = *(const uint32_t*)(r0 + 16);
            A[kt][3] = *(const uint32_t*)(r1 + 16);
        }
        const float* bias = mt ? bk : bq;
        const float bias0 = bias[g], bias1 = bias[g + 8];
        const float psc = mt ? 1.0f : QSCALE;
        #pragma unroll
        for (int nt = ntb; nt < ntb + 4; nt++) {
            float acc[4] = {bias0, bias0, bias1, bias1};
            #pragma unroll
            for (int kt = 0; kt < 8; kt++) {
                const char* bp = smc + OFX + (nt*8 + g)*SPX + kt*32 + t*4;
                uint32_t b0 = *(const uint32_t*)bp;
                uint32_t b1 = *(const uint32_t*)(bp + 16);
                mma_acc(acc, A[kt], b0, b1);
            }
            const int wcol = nt*8 + 2*t;
            *(uint32_t*)(smc + OFT + (mt*16 + g)*SPX + wcol*2) =
                bf2u(__floats2bfloat162_rn(acc[0]*psc, acc[1]*psc));
            *(uint32_t*)(smc + OFT + (mt*16 + g + 8)*SPX + wcol*2) =
                bf2u(__floats2bfloat162_rn(acc[2]*psc, acc[3]*psc));
        }
    }
    __syncthreads();

    {   // transpose qkT -> g_q/g_k [w][16]
        const int w = tid & 127, half = tid >> 7;
        uint32_t u[8];
        #pragma unroll
        for (int i = 0; i < 8; i++) {
            uint32_t lo = *(const uint16_t*)(smc + OFT + (half*16 + 2*i    )*SPX + w*2);
            uint32_t hi = *(const uint16_t*)(smc + OFT + (half*16 + 2*i + 1)*SPX + w*2);
            u[i] = lo | (hi << 16);
        }
        __nv_bfloat16* op = (half ? g_k : g_q) + (size_t)(b*WW + w0 + w)*DD;
        *(uint4*)op       = make_uint4(u[0], u[1], u[2], u[3]);
        *(uint4*)(op + 8) = make_uint4(u[4], u[5], u[6], u[7]);
    }
}

// ===========================================================================
// Kernel 2: row sums + fold 1/l into V. k B-frags now via ldmatrix.x4.
// ===========================================================================
#define SKD 48
__global__ void __launch_bounds__(256, 2) k_stats()
{
    __shared__ __align__(16) char smc[3*128*SKD];
    __shared__ float red[128];
    __shared__ uint32_t lpk[64];
    const uint32_t smb = smem_u32(smc);
    const int tid = threadIdx.x;
    const int wid = tid >> 5;
    const int lane = tid & 31;
    const int g = lane >> 2, t = lane & 3;
    const int b = blockIdx.y, j0 = blockIdx.x * 128;
    const uint32_t QS = smb, KS = smb + 128*SKD;

    // ldmatrix lane offset: matrix mi = lane>>3; rows (mi>>1)*8 + lane&7,
    // k-half byte (mi&1)*16.  x4 covers n-tiles (2p, 2p+1).
    const uint32_t mlane = (uint32_t)((((lane >> 4)*8 + (lane & 7))*SKD)
                                      + ((lane >> 3) & 1)*16);

    {
        int r = tid >> 1, h = tid & 1;
        CP16(QS + r*SKD + h*16, (const char*)(g_q + (size_t)(b*WW + j0 + r)*DD) + h*16);
    }
    {
        int r = tid >> 1, h = tid & 1;
        CP16(KS + r*SKD + h*16, (const char*)(g_k + (size_t)(b*WW + r)*DD) + h*16);
    }
    CP_COMMIT(); CP_WAIT0();
    __syncthreads();

    uint32_t a[4];
    {
        const char* r0 = smc + (wid*16 + g)*SKD + t*4;
        const char* r1 = smc + (wid*16 + g + 8)*SKD + t*4;
        a[0] = *(const uint32_t*)r0;
        a[1] = *(const uint32_t*)r1;
        a[2] = *(const uint32_t*)(r0 + 16);
        a[3] = *(const uint32_t*)(r1 + 16);
    }

    float l0 = 0.0f, l1 = 0.0f;
    for (int wt = 0; wt < 32; wt++) {
        const uint32_t kb = KS + (wt & 1)*(128*SKD) + mlane;
        if (wt + 1 < 32) {
            int r = tid >> 1, h = tid & 1;
            CP16(KS + ((wt + 1) & 1)*(128*SKD) + r*SKD + h*16,
                 (const char*)(g_k + (size_t)(b*WW + (wt + 1)*128 + r)*DD) + h*16);
        }
        CP_COMMIT();
        uint32_t acc01 = 0, acc23 = 0;
        #pragma unroll
        for (int p = 0; p < 8; p++) {
            uint32_t v0, v1, v2, v3;
            LDMX4(v0, v1, v2, v3, kb + (uint32_t)(p*(16*SKD)));
            #pragma unroll
            for (int h = 0; h < 2; h++) {
                float d[4];
                mma_z(d, a, h ? v2 : v0, h ? v3 : v1);
                uint32_t h01, h23;
                asm("cvt.rn.f16x2.f32 %0, %1, %2;" : "=r"(h01) : "f"(d[1]), "f"(d[0]));
                asm("cvt.rn.f16x2.f32 %0, %1, %2;" : "=r"(h23) : "f"(d[3]), "f"(d[2]));
                asm("ex2.approx.f16x2 %0, %0;" : "+r"(h01));
                asm("ex2.approx.f16x2 %0, %0;" : "+r"(h23));
                asm("add.rn.f16x2 %0, %0, %1;" : "+r"(acc01) : "r"(h01));
                asm("add.rn.f16x2 %0, %0, %1;" : "+r"(acc23) : "r"(h23));
            }
        }
        {
            float f0, f1, f2, f3;
            asm("{.reg .f16 lo, hi; mov.b32 {lo, hi}, %2; cvt.f32.f16 %0, lo; cvt.f32.f16 %1, hi;}"
                : "=f"(f0), "=f"(f1) : "r"(acc01));
            asm("{.reg .f16 lo, hi; mov.b32 {lo, hi}, %2; cvt.f32.f16 %0, lo; cvt.f32.f16 %1, hi;}"
                : "=f"(f2), "=f"(f3) : "r"(acc23));
            l0 += f0 + f1;
            l1 += f2 + f3;
        }
        CP_WAIT0();
        __syncthreads();
    }
    #pragma unroll
    for (int off = 1; off < 4; off <<= 1) {
        l0 += __shfl_down_sync(0xffffffffu, l0, off, 4);
        l1 += __shfl_down_sync(0xffffffffu, l1, off, 4);
    }
    if (t == 0) {
        red[wid*16 + g]     = 1.0f / l0;
        red[wid*16 + g + 8] = 1.0f / l1;
    }
    __syncthreads();
    if (tid < 64)
        lpk[tid] = bf2u(__floats2bfloat162_rn(red[2*tid], red[2*tid + 1]));
    __syncthreads();

    {
        const int chunk = tid & 15;
        const int cb    = tid >> 4;
        uint32_t s0 = lpk[chunk*4], s1 = lpk[chunk*4 + 1];
        uint32_t s2 = lpk[chunk*4 + 2], s3 = lpk[chunk*4 + 3];
        #pragma unroll
        for (int c = cb; c < 128; c += 16) {
            uint32_t* vp = (uint32_t*)(g_v + (size_t)(b*CC + c)*WW + j0 + chunk*8);
            uint4 v = *(uint4*)vp;
            asm("mul.rn.bf16x2 %0, %0, %1;" : "+r"(v.x) : "r"(s0));
            asm("mul.rn.bf16x2 %0, %0, %1;" : "+r"(v.y) : "r"(s1));
            asm("mul.rn.bf16x2 %0, %0, %1;" : "+r"(v.z) : "r"(s2));
            asm("mul.rn.bf16x2 %0, %0, %1;" : "+r"(v.w) : "r"(s3));
            *(uint4*)vp = v;
        }
    }
}

// ===========================================================================
// Kernel 3: context + residual; register-resident P; q B-frags via
// ldmatrix.x4. One sync per iteration.
// smem: ks@0 (6144), qring@6144 (4x3072), vs@18432 (2x18432) = 55296 B.
// ===========================================================================
#define SPJ 144
#define OF_KS 0
#define OF_QR 6144
#define OF_VS 18432

__global__ void __launch_bounds__(256, 2) k_ctx(const float* __restrict__ x,
                                                float* __restrict__ out)
{
    extern __shared__ __align__(16) char smc[];
    const uint32_t smb = smem_u32(smc);
    const int tid = threadIdx.x;
    const int wid = tid >> 5;
    const int lane = tid & 31;
    const int g = lane >> 2, t = lane & 3;
    const int b = blockIdx.y, w0 = blockIdx.x * 128;

    {
        int r = tid >> 1, h = tid & 1;
        CP16(smb + OF_KS + r*SKD + h*16,
             (const char*)(g_k + (size_t)(b*WW + w0 + r)*DD) + h*16);
    }
    {
        int r = tid >> 2, h = tid & 3;
        CP8(smb + OF_QR + r*SKD + h*8,
            (const char*)(g_q + (size_t)(b*WW + r)*DD) + h*8);
        CP8(smb + OF_QR + 3072 + r*SKD + h*8,
            (const char*)(g_q + (size_t)(b*WW + 64 + r)*DD) + h*8);
    }
    #pragma unroll
    for (int i = 0; i < 4; i++) {
        int cid = tid + i*256;
        int c = cid >> 3, ch = cid & 7;
        CP16(smb + OF_VS + c*SPJ + ch*16,
             (const char*)(g_v + (size_t)(b*CC + c)*WW) + ch*16);
    }
    CP_COMMIT(); CP_WAIT0();
    __syncthreads();

    uint32_t ak[4];
    {
        const char* r0 = smc + OF_KS + (wid*16 + g)*SKD + t*4;
        const char* r1 = smc + OF_KS + (wid*16 + g + 8)*SKD + t*4;
        ak[0] = *(const uint32_t*)r0;
        ak[1] = *(const uint32_t*)r1;
        ak[2] = *(const uint32_t*)(r0 + 16);
        ak[3] = *(const uint32_t*)(r1 + 16);
    }

    // ldmatrix lane offsets
    const uint32_t vlane = (uint32_t)((((lane >> 4)*8 + (lane & 7))*SPJ)
                                      + ((lane >> 3) & 1)*16);
    const uint32_t qlane = (uint32_t)((((lane >> 4)*8 + (lane & 7))*SKD)
                                      + ((lane >> 3) & 1)*16);

    float acc[16][4];
    #pragma unroll
    for (int ct = 0; ct < 16; ct++)
        #pragma unroll
        for (int e = 0; e < 4; e++) acc[ct][e] = 0.0f;

    for (int jt = 0; jt < 64; jt++) {
        if (jt + 2 < 64) {
            int r = tid >> 2, h = tid & 3;
            CP8(smb + OF_QR + ((jt + 2) & 3)*3072 + r*SKD + h*8,
                (const char*)(g_q + (size_t)(b*WW + (jt + 2)*64 + r)*DD) + h*8);
        }
        if (jt + 1 < 64) {
            #pragma unroll
            for (int i = 0; i < 4; i++) {
                int cid = tid + i*256;
                int c = cid >> 3, ch = cid & 7;
                CP16(smb + OF_VS + ((jt + 1) & 1)*18432 + c*SPJ + ch*16,
                     (const char*)(g_v + (size_t)(b*CC + c)*WW + (jt + 1)*64) + ch*16);
            }
        }
        CP_COMMIT();

        const uint32_t qb = smb + OF_QR + (jt & 3)*3072 + qlane;
        const uint32_t vb = smb + OF_VS + (jt & 1)*18432 + vlane;

        #pragma unroll
        for (int ks = 0; ks < 4; ks++) {
            // ---- QK for nt = 2ks, 2ks+1 -> P A-fragments (registers) ----
            uint32_t A[4];
            {
                uint32_t q0, q1, q2, q3;
                LDMX4(q0, q1, q2, q3, qb + (uint32_t)(ks*(16*SKD)));
                float d[4];
                mma_z(d, ak, q0, q1);
                asm("cvt.rn.bf16x2.f32 %0, %1, %2;" : "=r"(A[0]) : "f"(d[1]), "f"(d[0]));
                asm("cvt.rn.bf16x2.f32 %0, %1, %2;" : "=r"(A[1]) : "f"(d[3]), "f"(d[2]));
                mma_z(d, ak, q2, q3);
                asm("cvt.rn.bf16x2.f32 %0, %1, %2;" : "=r"(A[2]) : "f"(d[1]), "f"(d[0]));
                asm("cvt.rn.bf16x2.f32 %0, %1, %2;" : "=r"(A[3]) : "f"(d[3]), "f"(d[2]));
                asm("ex2.approx.ftz.bf16x2 %0, %0;" : "+r"(A[0]));
                asm("ex2.approx.ftz.bf16x2 %0, %0;" : "+r"(A[1]));
                asm("ex2.approx.ftz.bf16x2 %0, %0;" : "+r"(A[2]));
                asm("ex2.approx.ftz.bf16x2 %0, %0;" : "+r"(A[3]));
            }
            // ---- PV: out[w][c] += P x v^T, B frags via ldmatrix.x4 ----
            #pragma unroll
            for (int cp = 0; cp < 8; cp++) {
                uint32_t v0, v1, v2, v3;
                uint32_t ad = vb + (uint32_t)(cp*(16*SPJ) + ks*32);
                LDMX4(v0, v1, v2, v3, ad);
                mma_acc(acc[2*cp],     A, v0, v1);
                mma_acc(acc[2*cp + 1], A, v2, v3);
            }
        }
        CP_WAIT0();
        __syncthreads();
    }

    // ---- epilogue: out = acc + x ----
    const int wbase = w0 + wid*16;
    #pragma unroll
    for (int ct = 0; ct < 16; ct++) {
        size_t base = (size_t)(b*CC + ct*8 + 2*t)*WW + wbase;
        out[base + g]          = acc[ct][0] + x[base + g];
        out[base + g + 8]      = acc[ct][2] + x[base + g + 8];
        out[base + WW + g]     = acc[ct][1] + x[base + WW + g];
        out[base + WW + g + 8] = acc[ct][3] + x[base + WW + g + 8];
    }
}

// ===========================================================================
extern "C" void kernel_launch(void* const* d_in, const int* in_sizes, int n_in,
                              void* d_out, int out_size)
{
    const float* x  = (const float*)d_in[0];
    const float* Wq = (const float*)d_in[1];
    const float* bq = (const float*)d_in[2];
    const float* Wk = (const float*)d_in[3];
    const float* bk = (const float*)d_in[4];
    const float* Wv = (const float*)d_in[5];
    const float* bv = (const float*)d_in[6];
    float* out = (float*)d_out;

    const int smem_proj = 87040;
    const int smem_ctx  = 55296;
    cudaFuncSetAttribute(k_proj, cudaFuncAttributeMaxDynamicSharedMemorySize, smem_proj);
    cudaFuncSetAttribute(k_ctx,  cudaFuncAttributeMaxDynamicSharedMemorySize, smem_ctx);

    dim3 g(WW/128, BB);
    k_proj <<<g, 256, smem_proj>>>(x, Wq, bq, Wk, bk, Wv, bv);
    k_stats<<<g, 256>>>();
    k_ctx  <<<g, 256, smem_ctx>>>(x, out);
}